// round 1
// baseline (speedup 1.0000x reference)
#include <cuda_runtime.h>
#include <math.h>

// ---------------------------------------------------------------------------
// PsiQRHAttention  (B=2, S=2048, D_MODEL=1024, H=16, HD=64, D_LATENT=1024)
// fp32 SIMT baseline: tiled GEMMs + fused epilogues.
// ---------------------------------------------------------------------------

#define Bv 2
#define Sv 2048
#define DM 1024
#define NH 16
#define HD 64
#define DL 1024
#define TOK (Bv*Sv)          // 4096
#define LN_EPS 1e-5f
#define NORM_EPS 1e-12f

// ---- scratch (static device globals; allocation-free) ----
__device__ float g_Z  [(size_t)TOK * DL];          // 16 MB
__device__ float g_Q  [(size_t)TOK * DM];          // 16 MB
__device__ float g_R  [(size_t)TOK * DM];          // 16 MB
__device__ float g_H  [(size_t)TOK * DM];          // 16 MB
__device__ float g_Qc [(size_t)TOK * NH * 2 * HD]; // 33.5 MB
__device__ float g_Rc [(size_t)TOK * NH * 2 * HD]; // 33.5 MB
__device__ float g_S  [(size_t)Bv * NH * Sv * Sv]; // 512 MB
__device__ float g_Nrm[(size_t)Bv * NH * Sv];      // 256 KB
__device__ float g_AO [(size_t)TOK * DM];          // 16 MB

#define BM 64
#define BN 64
#define BK 16

// ---------------------------------------------------------------------------
// Batched strided GEMM, NN:  C[z] = A[z] @ B[z] (+bias) (* 1/max(norm,eps))
// z decomposes as (b = z/H, h = z%H); per-operand (b,h) strides.
// All dims are exact multiples of the tile in this problem -> no bounds checks.
// ---------------------------------------------------------------------------
__global__ void gemm_nn(const float* __restrict__ A, const float* __restrict__ B,
                        const float* __restrict__ bias, const float* __restrict__ rownorm,
                        float* __restrict__ C,
                        int M, int N, int K, int H,
                        long lda, long ldb, long ldc,
                        long sAb, long sAh, long sBb, long sBh,
                        long sCb, long sCh, long sRz)
{
    int z = blockIdx.z;
    int b = z / H, h = z - b * H;
    A += (long)b * sAb + (long)h * sAh;
    B += (long)b * sBb + (long)h * sBh;
    C += (long)b * sCb + (long)h * sCh;
    if (rownorm) rownorm += (long)z * sRz;

    __shared__ float As[BK][BM];
    __shared__ float Bs[BK][BN];

    int tid = threadIdx.x;            // 256 threads
    int tx = tid & 15, ty = tid >> 4; // 16x16
    int row0 = blockIdx.y * BM;
    int col0 = blockIdx.x * BN;

    // A-tile load map: each thread loads float4 A[row0+am][k0+ak .. +3]
    int am = tid >> 2;                // 0..63
    int ak = (tid & 3) << 2;          // 0,4,8,12
    // B-tile load map: float4 B[k0+bk][col0+bn .. +3]
    int bk = tid >> 4;                // 0..15
    int bn = (tid & 15) << 2;         // 0..60

    const float* Aptr = A + (long)(row0 + am) * lda + ak;
    const float* Bptr = B + (long)bk * ldb + col0 + bn;

    float acc[4][4] = {};

    for (int k0 = 0; k0 < K; k0 += BK) {
        float4 a4 = *(const float4*)Aptr;
        float4 b4 = *(const float4*)Bptr;
        As[ak + 0][am] = a4.x; As[ak + 1][am] = a4.y;
        As[ak + 2][am] = a4.z; As[ak + 3][am] = a4.w;
        *(float4*)&Bs[bk][bn] = b4;
        __syncthreads();
#pragma unroll
        for (int kk = 0; kk < BK; kk++) {
            float4 ra = *(const float4*)&As[kk][ty << 2];
            float4 rb = *(const float4*)&Bs[kk][tx << 2];
            float a[4] = {ra.x, ra.y, ra.z, ra.w};
            float bb[4] = {rb.x, rb.y, rb.z, rb.w};
#pragma unroll
            for (int i = 0; i < 4; i++)
#pragma unroll
                for (int j = 0; j < 4; j++)
                    acc[i][j] += a[i] * bb[j];
        }
        __syncthreads();
        Aptr += BK;
        Bptr += (long)BK * ldb;
    }

    float bias_r[4] = {0.f, 0.f, 0.f, 0.f};
    if (bias) {
        float4 b4 = *(const float4*)&bias[col0 + (tx << 2)];
        bias_r[0] = b4.x; bias_r[1] = b4.y; bias_r[2] = b4.z; bias_r[3] = b4.w;
    }
#pragma unroll
    for (int i = 0; i < 4; i++) {
        int m = row0 + (ty << 2) + i;
        float s = 1.0f;
        if (rownorm) s = 1.0f / fmaxf(rownorm[m], NORM_EPS);
        float4 o;
        o.x = (acc[i][0] + bias_r[0]) * s;
        o.y = (acc[i][1] + bias_r[1]) * s;
        o.z = (acc[i][2] + bias_r[2]) * s;
        o.w = (acc[i][3] + bias_r[3]) * s;
        *(float4*)&C[(long)m * ldc + col0 + (tx << 2)] = o;
    }
}

// ---------------------------------------------------------------------------
// Batched strided GEMM, NT:  C[z] = A[z] @ B[z]^T   (A: MxK, B: NxK row-major)
// ---------------------------------------------------------------------------
__global__ void gemm_nt(const float* __restrict__ A, const float* __restrict__ B,
                        float* __restrict__ C,
                        int M, int N, int K, int H,
                        long lda, long ldb, long ldc,
                        long sAb, long sAh, long sBb, long sBh,
                        long sCb, long sCh)
{
    int z = blockIdx.z;
    int b = z / H, h = z - b * H;
    A += (long)b * sAb + (long)h * sAh;
    B += (long)b * sBb + (long)h * sBh;
    C += (long)b * sCb + (long)h * sCh;

    __shared__ float As[BK][BM];
    __shared__ float Bs[BK][BN];

    int tid = threadIdx.x;
    int tx = tid & 15, ty = tid >> 4;
    int row0 = blockIdx.y * BM;
    int col0 = blockIdx.x * BN;

    int am = tid >> 2;
    int ak = (tid & 3) << 2;

    const float* Aptr = A + (long)(row0 + am) * lda + ak;
    const float* Bptr = B + (long)(col0 + am) * ldb + ak;   // rows of B are K-vectors

    float acc[4][4] = {};

    for (int k0 = 0; k0 < K; k0 += BK) {
        float4 a4 = *(const float4*)Aptr;
        float4 b4 = *(const float4*)Bptr;
        As[ak + 0][am] = a4.x; As[ak + 1][am] = a4.y;
        As[ak + 2][am] = a4.z; As[ak + 3][am] = a4.w;
        Bs[ak + 0][am] = b4.x; Bs[ak + 1][am] = b4.y;
        Bs[ak + 2][am] = b4.z; Bs[ak + 3][am] = b4.w;
        __syncthreads();
#pragma unroll
        for (int kk = 0; kk < BK; kk++) {
            float4 ra = *(const float4*)&As[kk][ty << 2];
            float4 rb = *(const float4*)&Bs[kk][tx << 2];
            float a[4] = {ra.x, ra.y, ra.z, ra.w};
            float bb[4] = {rb.x, rb.y, rb.z, rb.w};
#pragma unroll
            for (int i = 0; i < 4; i++)
#pragma unroll
                for (int j = 0; j < 4; j++)
                    acc[i][j] += a[i] * bb[j];
        }
        __syncthreads();
        Aptr += BK;
        Bptr += BK;
    }

#pragma unroll
    for (int i = 0; i < 4; i++) {
        int m = row0 + (ty << 2) + i;
        float4 o;
        o.x = acc[i][0]; o.y = acc[i][1]; o.z = acc[i][2]; o.w = acc[i][3];
        *(float4*)&C[(long)m * ldc + col0 + (tx << 2)] = o;
    }
}

// ---------------------------------------------------------------------------
// LayerNorm over last dim (DL=1024), in place. One block per row, 256 thr.
// ---------------------------------------------------------------------------
__global__ void layernorm_k(float* __restrict__ Z, const float* __restrict__ g,
                            const float* __restrict__ be)
{
    __shared__ float red[256];
    int tid = threadIdx.x;
    float* row = Z + (long)blockIdx.x * DL;

    float v[4];
#pragma unroll
    for (int t = 0; t < 4; t++) v[t] = row[tid + t * 256];

    float s = v[0] + v[1] + v[2] + v[3];
    red[tid] = s; __syncthreads();
    for (int off = 128; off > 0; off >>= 1) {
        if (tid < off) red[tid] += red[tid + off];
        __syncthreads();
    }
    float mu = red[0] * (1.0f / DL);
    __syncthreads();

    float vs = 0.f;
#pragma unroll
    for (int t = 0; t < 4; t++) { float d = v[t] - mu; vs += d * d; }
    red[tid] = vs; __syncthreads();
    for (int off = 128; off > 0; off >>= 1) {
        if (tid < off) red[tid] += red[tid + off];
        __syncthreads();
    }
    float rstd = rsqrtf(red[0] * (1.0f / DL) + LN_EPS);

#pragma unroll
    for (int t = 0; t < 4; t++) {
        int i = tid + t * 256;
        row[i] = (v[t] - mu) * rstd * g[i] + be[i];
    }
}

// ---------------------------------------------------------------------------
// Phasor: phi = q_row @ Wphi + bphi ;  out = [q*cos(phi) | q*sin(phi)]
// one block per token (256 thr = 4 heads x 64 lanes), Wphi cached in smem.
// ---------------------------------------------------------------------------
__global__ void phasor_k(const float* __restrict__ Qin, float* __restrict__ Qc,
                         const float* __restrict__ Wphi, const float* __restrict__ bphi)
{
    __shared__ float W[HD][HD];      // W[d][j]
    __shared__ float qrow[4][HD + 4];
    int tid = threadIdx.x;
    int j = tid & 63, g = tid >> 6;  // head-group lane / group 0..3

    for (int i = tid; i < HD * HD; i += 256) W[i >> 6][i & 63] = Wphi[i];
    __syncthreads();

    const float* base = Qin + (long)blockIdx.x * (NH * HD);
    float* obase = Qc + (long)blockIdx.x * (NH * 2 * HD);
    float bj = bphi[j];

    for (int hb = 0; hb < NH; hb += 4) {
        int h = hb + g;
        qrow[g][j] = base[h * HD + j];
        __syncthreads();
        float phi = bj;
#pragma unroll 16
        for (int d = 0; d < HD; d++) phi += qrow[g][d] * W[d][j];
        float q = qrow[g][j];
        float sp, cp;
        sincosf(phi, &sp, &cp);
        obase[h * 2 * HD + j]      = q * cp;
        obase[h * 2 * HD + HD + j] = q * sp;
        __syncthreads();
    }
}

// ---------------------------------------------------------------------------
// Row L2 norms of scores: norms[row] = sqrt(sum_k scores[row][k]^2)
// one block (256 thr) per row of length S.
// ---------------------------------------------------------------------------
__global__ void rownorm_k(const float* __restrict__ S_, float* __restrict__ nrm)
{
    __shared__ float red[256];
    int tid = threadIdx.x;
    const float* p = S_ + (long)blockIdx.x * Sv;
    float s = 0.f;
#pragma unroll
    for (int t = 0; t < Sv / 256; t++) {
        float v = p[tid + t * 256];
        s += v * v;
    }
    red[tid] = s; __syncthreads();
    for (int off = 128; off > 0; off >>= 1) {
        if (tid < off) red[tid] += red[tid + off];
        __syncthreads();
    }
    if (tid == 0) nrm[blockIdx.x] = sqrtf(red[0]);
}

// ---------------------------------------------------------------------------
extern "C" void kernel_launch(void* const* d_in, const int* in_sizes, int n_in,
                              void* d_out, int out_size)
{
    const float* query = (const float*)d_in[0];
    // d_in[1] key_in, d_in[2] value: intentionally unused (reference ignores them)
    const float* Wz   = (const float*)d_in[3];
    const float* bz   = (const float*)d_in[4];
    const float* ln_g = (const float*)d_in[5];
    const float* ln_b = (const float*)d_in[6];
    const float* Wq   = (const float*)d_in[7];
    const float* bq   = (const float*)d_in[8];
    const float* Wr   = (const float*)d_in[9];
    const float* br   = (const float*)d_in[10];
    const float* Wh   = (const float*)d_in[11];
    const float* bh   = (const float*)d_in[12];
    const float* Wphi = (const float*)d_in[13];
    const float* bphi = (const float*)d_in[14];
    const float* Wo   = (const float*)d_in[15];
    const float* bo   = (const float*)d_in[16];
    float* out = (float*)d_out;

    float *Z, *Q, *R, *Hh, *Qc, *Rc, *Sc, *Nm, *Ao;
    cudaGetSymbolAddress((void**)&Z,  g_Z);
    cudaGetSymbolAddress((void**)&Q,  g_Q);
    cudaGetSymbolAddress((void**)&R,  g_R);
    cudaGetSymbolAddress((void**)&Hh, g_H);
    cudaGetSymbolAddress((void**)&Qc, g_Qc);
    cudaGetSymbolAddress((void**)&Rc, g_Rc);
    cudaGetSymbolAddress((void**)&Sc, g_S);
    cudaGetSymbolAddress((void**)&Nm, g_Nrm);
    cudaGetSymbolAddress((void**)&Ao, g_AO);

    dim3 blk(256);

    // 1) Z = query @ Wz + bz        [4096,1024]x[1024,1024]
    gemm_nn<<<dim3(DL / BN, TOK / BM, 1), blk>>>(
        query, Wz, bz, nullptr, Z,
        TOK, DL, DM, 1, DM, DL, DL,
        0, 0, 0, 0, 0, 0, 0);

    // 2) LayerNorm in place
    layernorm_k<<<TOK, blk>>>(Z, ln_g, ln_b);

    // 3) Q/R/H projections
    gemm_nn<<<dim3(DM / BN, TOK / BM, 1), blk>>>(
        Z, Wq, bq, nullptr, Q,
        TOK, DM, DL, 1, DL, DM, DM, 0, 0, 0, 0, 0, 0, 0);
    gemm_nn<<<dim3(DM / BN, TOK / BM, 1), blk>>>(
        Z, Wr, br, nullptr, R,
        TOK, DM, DL, 1, DL, DM, DM, 0, 0, 0, 0, 0, 0, 0);
    gemm_nn<<<dim3(DM / BN, TOK / BM, 1), blk>>>(
        Z, Wh, bh, nullptr, Hh,
        TOK, DM, DL, 1, DL, DM, DM, 0, 0, 0, 0, 0, 0, 0);

    // 4) Phasor -> Qc, Rc  [B,S,H,128]
    phasor_k<<<TOK, blk>>>(Q, Qc, Wphi, bphi);
    phasor_k<<<TOK, blk>>>(R, Rc, Wphi, bphi);

    // 5) scores[b,h] = Qc[b,:,h,:] @ Rc[b,:,h,:]^T     (32 batched NT, K=128)
    {
        long sTok = (long)Sv * (NH * 2 * HD);   // per-b stride in Qc/Rc
        gemm_nt<<<dim3(Sv / BN, Sv / BM, Bv * NH), blk>>>(
            Qc, Rc, Sc,
            Sv, Sv, 2 * HD, NH,
            NH * 2 * HD, NH * 2 * HD, Sv,
            sTok, 2 * HD, sTok, 2 * HD,
            (long)NH * Sv * Sv, (long)Sv * Sv);
    }

    // 6) per-row L2 norms
    rownorm_k<<<Bv * NH * Sv, blk>>>(Sc, Nm);

    // 7) attn_out[b,q,h,:] = (1/norm_q) * scores[b,h,q,:] @ Hv[b,:,h,:]
    gemm_nn<<<dim3(HD / BN, Sv / BM, Bv * NH), blk>>>(
        Sc, Hh, nullptr, Nm, Ao,
        Sv, HD, Sv, NH,
        Sv, DM, DM,
        (long)NH * Sv * Sv, (long)Sv * Sv,
        (long)Sv * DM, HD,
        (long)Sv * DM, HD,
        Sv);

    // 8) out = attn_out @ Wo + bo
    gemm_nn<<<dim3(DM / BN, TOK / BM, 1), blk>>>(
        Ao, Wo, bo, nullptr, out,
        TOK, DM, DM, 1, DM, DM, DM, 0, 0, 0, 0, 0, 0, 0);
}

// round 3
// speedup vs baseline: 2.1223x; 2.1223x over previous
#include <cuda_runtime.h>
#include <cuda_bf16.h>
#include <math.h>
#include <stdint.h>

#define Bv 2
#define Sv 2048
#define DM 1024
#define NH 16
#define HD 64
#define DL 1024
#define TOK (Bv*Sv)          // 4096
#define LN_EPS 1e-5f
#define NORM_EPS 1e-12f

// ---- scratch (static device globals; allocation-free) ----
__device__ float g_Z  [(size_t)TOK * DL];
__device__ float g_Q  [(size_t)TOK * DM];
__device__ float g_R  [(size_t)TOK * DM];
__device__ float g_H  [(size_t)TOK * DM];
__device__ float g_Qc [(size_t)TOK * NH * 2 * HD];
__device__ float g_Rc [(size_t)TOK * NH * 2 * HD];
__device__ float g_S  [(size_t)Bv * NH * Sv * Sv];   // 512 MB scores
__device__ float g_Nrm[(size_t)Bv * NH * Sv];        // sumsq -> norm
__device__ float g_AO [(size_t)TOK * DM];
__device__ float g_WT [5 * (size_t)DM * DL];         // transposed weights
__device__ float g_HvT[(size_t)Bv * NH * HD * Sv];   // Hv^T per (b,h)

// ===========================================================================
// helpers
// ===========================================================================
__device__ __forceinline__ void mma_bf16(float* d, const uint32_t* a, const uint32_t* b) {
    asm volatile(
        "mma.sync.aligned.m16n8k16.row.col.f32.bf16.bf16.f32 "
        "{%0,%1,%2,%3}, {%4,%5,%6,%7}, {%8,%9}, {%0,%1,%2,%3};"
        : "+f"(d[0]), "+f"(d[1]), "+f"(d[2]), "+f"(d[3])
        : "r"(a[0]), "r"(a[1]), "r"(a[2]), "r"(a[3]), "r"(b[0]), "r"(b[1]));
}
__device__ __forceinline__ uint32_t pack2bf(float a, float b) {
    __nv_bfloat162 t = __floats2bfloat162_rn(a, b);   // x=a (low), y=b (high)
    return *reinterpret_cast<uint32_t*>(&t);
}
// split v -> hi (bf16) + lo (bf16 of residual); returns packed pairs
__device__ __forceinline__ void split4(float4 v, uint32_t& h01, uint32_t& h23,
                                       uint32_t& l01, uint32_t& l23) {
    __nv_bfloat16 hx = __float2bfloat16(v.x), hy = __float2bfloat16(v.y);
    __nv_bfloat16 hz = __float2bfloat16(v.z), hw = __float2bfloat16(v.w);
    float lx = v.x - __bfloat162float(hx), ly = v.y - __bfloat162float(hy);
    float lz = v.z - __bfloat162float(hz), lw = v.w - __bfloat162float(hw);
    __nv_bfloat162 h0 = {hx, hy}, h1 = {hz, hw};
    h01 = *reinterpret_cast<uint32_t*>(&h0);
    h23 = *reinterpret_cast<uint32_t*>(&h1);
    l01 = pack2bf(lx, ly);
    l23 = pack2bf(lz, lw);
}

// ===========================================================================
// Batched NT GEMM, 3xbf16 split: C[z](MxN) = A[z](MxK,K-major) @ B[z](NxK,K-major)^T
// epilogue: +bias(col), *1/max(rnorm(row),eps), optional row-sumsq atomics
// BM=128, BK=32, 512 threads (16 warps, warp tile 32 x BN/4)
// ===========================================================================
template<int BN>
__global__ void __launch_bounds__(512, 1)
gemm_bf16x3(const float* __restrict__ A, const float* __restrict__ B,
            const float* __restrict__ bias, const float* __restrict__ rnorm,
            float* __restrict__ nrmsq, float* __restrict__ C,
            int K, int H,
            long lda, long ldb, long ldc,
            long sAb, long sAh, long sBb, long sBh, long sCb, long sCh,
            long sNz)
{
    constexpr int BM = 128, BK = 32;
    constexpr int PA = 40;                     // smem row pitch (bf16 elements)
    constexpr int NI = BN / 32;                // n8 tiles per warp (4 or 2)
    constexpr int ACH = 2;                     // A float4 loads per thread
    constexpr int BCH = (BN * 8) / 512;        // B float4 loads per thread (2 or 1)
    constexpr int OFF_AH = 0;
    constexpr int OFF_AL = OFF_AH + BM * PA;   // offsets in bf16 elements
    constexpr int OFF_BH = OFF_AL + BM * PA;
    constexpr int OFF_BL = OFF_BH + BN * PA;
    constexpr int SP = BN + 4;                 // staging pitch (floats)

    extern __shared__ char smem_raw[];
    __nv_bfloat16* sm = (__nv_bfloat16*)smem_raw;
    float* stg = (float*)smem_raw;

    int tid = threadIdx.x, wid = tid >> 5, lane = tid & 31;
    int gid = lane >> 2, tig = lane & 3;
    int wm0 = (wid >> 2) * 32;                 // warp row origin (4 m-warps)
    int wn0 = (wid & 3) * (BN / 4);            // warp col origin (4 n-warps)

    int z = blockIdx.z, b = z / H, h = z - b * H;
    int row0 = blockIdx.y * BM, col0 = blockIdx.x * BN;
    A += (long)b * sAb + (long)h * sAh + (long)row0 * lda;
    B += (long)b * sBb + (long)h * sBh + (long)col0 * ldb;
    C += (long)b * sCb + (long)h * sCh;
    if (rnorm) rnorm += (long)z * sNz;
    if (nrmsq) nrmsq += (long)z * sNz;

    // load maps
    const float* pa[ACH]; int sa[ACH];
    const float* pb[BCH]; int sbo[BCH];
#pragma unroll
    for (int i = 0; i < ACH; i++) {
        int idx = tid + i * 512; int r = idx >> 3, kc = idx & 7;
        pa[i] = A + (long)r * lda + kc * 4;
        sa[i] = r * PA + kc * 4;
    }
#pragma unroll
    for (int i = 0; i < BCH; i++) {
        int idx = tid + i * 512; int r = idx >> 3, kc = idx & 7;
        pb[i] = B + (long)r * ldb + kc * 4;
        sbo[i] = r * PA + kc * 4;
    }

    float acc[2][NI][4];
#pragma unroll
    for (int mi = 0; mi < 2; mi++)
#pragma unroll
        for (int ni = 0; ni < NI; ni++)
#pragma unroll
            for (int j = 0; j < 4; j++) acc[mi][ni][j] = 0.f;

    const int NS = K / BK;
    float4 ra[ACH], rb[BCH];
#pragma unroll
    for (int i = 0; i < ACH; i++) { ra[i] = *(const float4*)pa[i]; pa[i] += BK; }
#pragma unroll
    for (int i = 0; i < BCH; i++) { rb[i] = *(const float4*)pb[i]; pb[i] += BK; }

    for (int s = 0; s < NS; s++) {
        // convert + store stage s
#pragma unroll
        for (int i = 0; i < ACH; i++) {
            uint32_t h01, h23, l01, l23;
            split4(ra[i], h01, h23, l01, l23);
            *(uint2*)(sm + OFF_AH + sa[i]) = make_uint2(h01, h23);
            *(uint2*)(sm + OFF_AL + sa[i]) = make_uint2(l01, l23);
        }
#pragma unroll
        for (int i = 0; i < BCH; i++) {
            uint32_t h01, h23, l01, l23;
            split4(rb[i], h01, h23, l01, l23);
            *(uint2*)(sm + OFF_BH + sbo[i]) = make_uint2(h01, h23);
            *(uint2*)(sm + OFF_BL + sbo[i]) = make_uint2(l01, l23);
        }
        __syncthreads();
        if (s + 1 < NS) {   // prefetch next stage (overlaps the MMA section)
#pragma unroll
            for (int i = 0; i < ACH; i++) { ra[i] = *(const float4*)pa[i]; pa[i] += BK; }
#pragma unroll
            for (int i = 0; i < BCH; i++) { rb[i] = *(const float4*)pb[i]; pb[i] += BK; }
        }
#pragma unroll
        for (int k16 = 0; k16 < 32; k16 += 16) {
            uint32_t ah[2][4], al[2][4], bh[NI][2], bl[NI][2];
#pragma unroll
            for (int mi = 0; mi < 2; mi++) {
                int r = wm0 + mi * 16 + gid;
                int c = k16 + tig * 2;
                ah[mi][0] = *(const uint32_t*)(sm + OFF_AH + r * PA + c);
                ah[mi][1] = *(const uint32_t*)(sm + OFF_AH + (r + 8) * PA + c);
                ah[mi][2] = *(const uint32_t*)(sm + OFF_AH + r * PA + c + 8);
                ah[mi][3] = *(const uint32_t*)(sm + OFF_AH + (r + 8) * PA + c + 8);
                al[mi][0] = *(const uint32_t*)(sm + OFF_AL + r * PA + c);
                al[mi][1] = *(const uint32_t*)(sm + OFF_AL + (r + 8) * PA + c);
                al[mi][2] = *(const uint32_t*)(sm + OFF_AL + r * PA + c + 8);
                al[mi][3] = *(const uint32_t*)(sm + OFF_AL + (r + 8) * PA + c + 8);
            }
#pragma unroll
            for (int ni = 0; ni < NI; ni++) {
                int n = wn0 + ni * 8 + gid;
                int c = k16 + tig * 2;
                bh[ni][0] = *(const uint32_t*)(sm + OFF_BH + n * PA + c);
                bh[ni][1] = *(const uint32_t*)(sm + OFF_BH + n * PA + c + 8);
                bl[ni][0] = *(const uint32_t*)(sm + OFF_BL + n * PA + c);
                bl[ni][1] = *(const uint32_t*)(sm + OFF_BL + n * PA + c + 8);
            }
#pragma unroll
            for (int mi = 0; mi < 2; mi++)
#pragma unroll
                for (int ni = 0; ni < NI; ni++) {
                    mma_bf16(acc[mi][ni], ah[mi], bh[ni]);
                    mma_bf16(acc[mi][ni], ah[mi], bl[ni]);
                    mma_bf16(acc[mi][ni], al[mi], bh[ni]);
                }
        }
        __syncthreads();
    }

    // ---- epilogue: regs -> smem staging -> fused epilogue + coalesced STG ----
#pragma unroll
    for (int mi = 0; mi < 2; mi++)
#pragma unroll
        for (int ni = 0; ni < NI; ni++) {
            int r = wm0 + mi * 16 + gid;
            int c = wn0 + ni * 8 + tig * 2;
            stg[r * SP + c]           = acc[mi][ni][0];
            stg[r * SP + c + 1]       = acc[mi][ni][1];
            stg[(r + 8) * SP + c]     = acc[mi][ni][2];
            stg[(r + 8) * SP + c + 1] = acc[mi][ni][3];
        }
    __syncthreads();

    if (nrmsq && tid < BM) {
        float ssum = 0.f;
        const float* p = stg + tid * SP;
#pragma unroll 8
        for (int j = 0; j < BN; j++) { float v = p[j]; ssum += v * v; }
        atomicAdd(&nrmsq[row0 + tid], ssum);
    }
#pragma unroll
    for (int i = 0; i < BN / 16; i++) {
        int idx = tid + i * 512;
        int row = idx / (BN / 4), c4 = (idx % (BN / 4)) * 4;
        float4 v = *(const float4*)(stg + row * SP + c4);
        int col = col0 + c4;
        if (bias) {
            float4 bv = *(const float4*)&bias[col];
            v.x += bv.x; v.y += bv.y; v.z += bv.z; v.w += bv.w;
        }
        if (rnorm) {
            float sc = 1.0f / fmaxf(rnorm[row0 + row], NORM_EPS);
            v.x *= sc; v.y *= sc; v.z *= sc; v.w *= sc;
        }
        *(float4*)&C[(long)(row0 + row) * ldc + col] = v;
    }
}

// ===========================================================================
// tiled transpose: out[x][y] = in[y][x]  (batched)
// ===========================================================================
__global__ void transpose_k(const float* __restrict__ in, float* __restrict__ out,
                            long ldi, long ldo, int H,
                            long sIb, long sIh, long sOz)
{
    __shared__ float t[32][33];
    int z = blockIdx.z, b = z / H, h = z - b * H;
    in  += (long)b * sIb + (long)h * sIh;
    out += (long)z * sOz;
    int x0 = blockIdx.x * 32, y0 = blockIdx.y * 32;
    int tx = threadIdx.x & 31, ty = threadIdx.x >> 5;  // 32 x 8
#pragma unroll
    for (int i = 0; i < 4; i++)
        t[ty + i * 8][tx] = in[(long)(y0 + ty + i * 8) * ldi + x0 + tx];
    __syncthreads();
#pragma unroll
    for (int i = 0; i < 4; i++)
        out[(long)(x0 + ty + i * 8) * ldo + y0 + tx] = t[tx][ty + i * 8];
}

// ===========================================================================
// LayerNorm over last dim (DL=1024), in place.
// ===========================================================================
__global__ void layernorm_k(float* __restrict__ Z, const float* __restrict__ g,
                            const float* __restrict__ be)
{
    __shared__ float red[256];
    int tid = threadIdx.x;
    float* row = Z + (long)blockIdx.x * DL;
    float v[4];
#pragma unroll
    for (int t = 0; t < 4; t++) v[t] = row[tid + t * 256];
    float s = v[0] + v[1] + v[2] + v[3];
    red[tid] = s; __syncthreads();
    for (int off = 128; off > 0; off >>= 1) {
        if (tid < off) red[tid] += red[tid + off];
        __syncthreads();
    }
    float mu = red[0] * (1.0f / DL);
    __syncthreads();
    float vs = 0.f;
#pragma unroll
    for (int t = 0; t < 4; t++) { float d = v[t] - mu; vs += d * d; }
    red[tid] = vs; __syncthreads();
    for (int off = 128; off > 0; off >>= 1) {
        if (tid < off) red[tid] += red[tid + off];
        __syncthreads();
    }
    float rstd = rsqrtf(red[0] * (1.0f / DL) + LN_EPS);
#pragma unroll
    for (int t = 0; t < 4; t++) {
        int i = tid + t * 256;
        row[i] = (v[t] - mu) * rstd * g[i] + be[i];
    }
}

// ===========================================================================
// Phasor: phi = q_row @ Wphi + bphi ; out = [q*cos(phi) | q*sin(phi)]
// ===========================================================================
__global__ void phasor_k(const float* __restrict__ Qin, float* __restrict__ Qc,
                         const float* __restrict__ Wphi, const float* __restrict__ bphi)
{
    __shared__ float W[HD][HD];
    __shared__ float qrow[4][HD + 4];
    int tid = threadIdx.x;
    int j = tid & 63, g = tid >> 6;
    for (int i = tid; i < HD * HD; i += 256) W[i >> 6][i & 63] = Wphi[i];
    __syncthreads();
    const float* base = Qin + (long)blockIdx.x * (NH * HD);
    float* obase = Qc + (long)blockIdx.x * (NH * 2 * HD);
    float bj = bphi[j];
    for (int hb = 0; hb < NH; hb += 4) {
        int h = hb + g;
        qrow[g][j] = base[h * HD + j];
        __syncthreads();
        float phi = bj;
#pragma unroll 16
        for (int d = 0; d < HD; d++) phi += qrow[g][d] * W[d][j];
        float q = qrow[g][j];
        float sp, cp;
        sincosf(phi, &sp, &cp);
        obase[h * 2 * HD + j]      = q * cp;
        obase[h * 2 * HD + HD + j] = q * sp;
        __syncthreads();
    }
}

__global__ void sqrt_k(float* __restrict__ p, int n)
{
    int i = blockIdx.x * 256 + threadIdx.x;
    if (i < n) p[i] = sqrtf(p[i]);
}

// ===========================================================================
extern "C" void kernel_launch(void* const* d_in, const int* in_sizes, int n_in,
                              void* d_out, int out_size)
{
    const float* query = (const float*)d_in[0];
    const float* Wz   = (const float*)d_in[3];
    const float* bz   = (const float*)d_in[4];
    const float* ln_g = (const float*)d_in[5];
    const float* ln_b = (const float*)d_in[6];
    const float* Wq   = (const float*)d_in[7];
    const float* bq   = (const float*)d_in[8];
    const float* Wr   = (const float*)d_in[9];
    const float* br   = (const float*)d_in[10];
    const float* Wh   = (const float*)d_in[11];
    const float* bh   = (const float*)d_in[12];
    const float* Wphi = (const float*)d_in[13];
    const float* bphi = (const float*)d_in[14];
    const float* Wo   = (const float*)d_in[15];
    const float* bo   = (const float*)d_in[16];
    float* out = (float*)d_out;

    float *Z, *Q, *R, *Hh, *Qc, *Rc, *Sc, *Nm, *Ao, *WT, *HvT;
    cudaGetSymbolAddress((void**)&Z,   g_Z);
    cudaGetSymbolAddress((void**)&Q,   g_Q);
    cudaGetSymbolAddress((void**)&R,   g_R);
    cudaGetSymbolAddress((void**)&Hh,  g_H);
    cudaGetSymbolAddress((void**)&Qc,  g_Qc);
    cudaGetSymbolAddress((void**)&Rc,  g_Rc);
    cudaGetSymbolAddress((void**)&Sc,  g_S);
    cudaGetSymbolAddress((void**)&Nm,  g_Nrm);
    cudaGetSymbolAddress((void**)&Ao,  g_AO);
    cudaGetSymbolAddress((void**)&WT,  g_WT);
    cudaGetSymbolAddress((void**)&HvT, g_HvT);

    // dynamic smem: max(kbuf, staging)
    const int SM128 = 128 * (128 + 4) * 4;               // 67,584 (staging dominates)
    const int SM64_kbuf = (128 + 64) * 40 * 2 * 2;       // 30,720
    const int SM64_stg  = 128 * (64 + 4) * 4;            // 34,816
    const int SM64 = SM64_stg > SM64_kbuf ? SM64_stg : SM64_kbuf;
    cudaFuncSetAttribute(gemm_bf16x3<128>, cudaFuncAttributeMaxDynamicSharedMemorySize, SM128);
    cudaFuncSetAttribute(gemm_bf16x3<64>,  cudaFuncAttributeMaxDynamicSharedMemorySize, SM64);

    dim3 blk(256), gblk(512);
    long szW = (long)DM * DL;
    float* WzT = WT + 0 * szW;
    float* WqT = WT + 1 * szW;
    float* WrT = WT + 2 * szW;
    float* WhT = WT + 3 * szW;
    float* WoT = WT + 4 * szW;

    // 0) transpose weights -> K-major B operands
    transpose_k<<<dim3(32, 32, 1), blk>>>(Wz, WzT, DL, DM, 1, 0, 0, 0);
    transpose_k<<<dim3(32, 32, 1), blk>>>(Wq, WqT, DM, DL, 1, 0, 0, 0);
    transpose_k<<<dim3(32, 32, 1), blk>>>(Wr, WrT, DM, DL, 1, 0, 0, 0);
    transpose_k<<<dim3(32, 32, 1), blk>>>(Wh, WhT, DM, DL, 1, 0, 0, 0);
    transpose_k<<<dim3(32, 32, 1), blk>>>(Wo, WoT, DM, DM, 1, 0, 0, 0);

    // 1) Z = query @ Wz + bz
    gemm_bf16x3<128><<<dim3(DL / 128, TOK / 128, 1), gblk, SM128>>>(
        query, WzT, bz, nullptr, nullptr, Z,
        DM, 1, DM, DM, DL, 0, 0, 0, 0, 0, 0, 0);

    // 2) LayerNorm
    layernorm_k<<<TOK, blk>>>(Z, ln_g, ln_b);

    // 3) Q/R/H projections
    gemm_bf16x3<128><<<dim3(DM / 128, TOK / 128, 1), gblk, SM128>>>(
        Z, WqT, bq, nullptr, nullptr, Q, DL, 1, DL, DL, DM, 0, 0, 0, 0, 0, 0, 0);
    gemm_bf16x3<128><<<dim3(DM / 128, TOK / 128, 1), gblk, SM128>>>(
        Z, WrT, br, nullptr, nullptr, R, DL, 1, DL, DL, DM, 0, 0, 0, 0, 0, 0, 0);
    gemm_bf16x3<128><<<dim3(DM / 128, TOK / 128, 1), gblk, SM128>>>(
        Z, WhT, bh, nullptr, nullptr, Hh, DL, 1, DL, DL, DM, 0, 0, 0, 0, 0, 0, 0);

    // 4) phasor -> Qc, Rc
    phasor_k<<<TOK, blk>>>(Q, Qc, Wphi, bphi);
    phasor_k<<<TOK, blk>>>(R, Rc, Wphi, bphi);

    // 5) Hv^T per (b,h): [S][64] -> [64][S]
    transpose_k<<<dim3(HD / 32, Sv / 32, Bv * NH), blk>>>(
        Hh, HvT, DM, Sv, NH, (long)Sv * DM, HD, (long)HD * Sv);

    // 6) zero sumsq accumulator
    cudaMemsetAsync(Nm, 0, (size_t)Bv * NH * Sv * sizeof(float));

    // 7) scores = Qc @ Rc^T, fused row-sumsq atomics
    gemm_bf16x3<128><<<dim3(Sv / 128, Sv / 128, Bv * NH), gblk, SM128>>>(
        Qc, Rc, nullptr, nullptr, Nm, Sc,
        2 * HD, NH,
        NH * 2 * HD, NH * 2 * HD, Sv,
        (long)Sv * NH * 2 * HD, 2 * HD,
        (long)Sv * NH * 2 * HD, 2 * HD,
        (long)NH * Sv * Sv, (long)Sv * Sv,
        Sv);

    // 8) norm = sqrt(sumsq)
    sqrt_k<<<(Bv * NH * Sv + 255) / 256, blk>>>(Nm, Bv * NH * Sv);

    // 9) attn_out = (scores/norm) @ Hv     (B = HvT, K-major)
    gemm_bf16x3<64><<<dim3(1, Sv / 128, Bv * NH), gblk, SM64>>>(
        Sc, HvT, nullptr, Nm, nullptr, Ao,
        Sv, NH,
        Sv, Sv, DM,
        (long)NH * Sv * Sv, (long)Sv * Sv,
        (long)NH * HD * Sv, (long)HD * Sv,
        (long)Sv * DM, HD,
        Sv);

    // 10) out = attn_out @ Wo + bo
    gemm_bf16x3<128><<<dim3(DM / 128, TOK / 128, 1), gblk, SM128>>>(
        Ao, WoT, bo, nullptr, nullptr, out,
        DM, 1, DM, DM, DM, 0, 0, 0, 0, 0, 0, 0);
}

// round 4
// speedup vs baseline: 2.4948x; 1.1755x over previous
#include <cuda_runtime.h>
#include <cuda_bf16.h>
#include <math.h>
#include <stdint.h>

typedef __nv_bfloat16 bf16;

#define Bv 2
#define Sv 2048
#define DM 1024
#define NH 16
#define HD 64
#define DL 1024
#define TOK (Bv*Sv)          // 4096
#define LN_EPS 1e-5f
#define NORM_EPS 1e-12f

// ---- scratch (static device globals; allocation-free) ----
__device__ bf16  g_Qs_h[(size_t)TOK * DM],  g_Qs_l[(size_t)TOK * DM];
__device__ bf16  g_WT_h[5 * (size_t)DM * DL], g_WT_l[5 * (size_t)DM * DL];
__device__ float g_Z  [(size_t)TOK * DL];
__device__ bf16  g_Zs_h[(size_t)TOK * DL],  g_Zs_l[(size_t)TOK * DL];
__device__ float g_Q  [(size_t)TOK * DM];
__device__ float g_R  [(size_t)TOK * DM];
__device__ float g_H  [(size_t)TOK * DM];
__device__ bf16  g_Qc_h[(size_t)TOK * NH * 2 * HD], g_Qc_l[(size_t)TOK * NH * 2 * HD];
__device__ bf16  g_Rc_h[(size_t)TOK * NH * 2 * HD], g_Rc_l[(size_t)TOK * NH * 2 * HD];
__device__ bf16  g_Sc_h[(size_t)Bv * NH * Sv * Sv];   // 256 MB
__device__ bf16  g_Sc_l[(size_t)Bv * NH * Sv * Sv];   // 256 MB
__device__ float g_Nrm[(size_t)Bv * NH * Sv];
__device__ bf16  g_HvT_h[(size_t)Bv * NH * HD * Sv], g_HvT_l[(size_t)Bv * NH * HD * Sv];
__device__ bf16  g_Ao_h[(size_t)TOK * DM], g_Ao_l[(size_t)TOK * DM];

// ===========================================================================
// helpers
// ===========================================================================
__device__ __forceinline__ uint32_t smem_u32(const void* p) {
    uint32_t a;
    asm("{ .reg .u64 t; cvta.to.shared.u64 t, %1; cvt.u32.u64 %0, t; }"
        : "=r"(a) : "l"(p));
    return a;
}
__device__ __forceinline__ void mma_bf16(float* d, const uint32_t* a, const uint32_t* b) {
    asm volatile(
        "mma.sync.aligned.m16n8k16.row.col.f32.bf16.bf16.f32 "
        "{%0,%1,%2,%3}, {%4,%5,%6,%7}, {%8,%9}, {%0,%1,%2,%3};"
        : "+f"(d[0]), "+f"(d[1]), "+f"(d[2]), "+f"(d[3])
        : "r"(a[0]), "r"(a[1]), "r"(a[2]), "r"(a[3]), "r"(b[0]), "r"(b[1]));
}
__device__ __forceinline__ void cpa16(uint32_t dst, const void* src) {
    asm volatile("cp.async.cg.shared.global [%0], [%1], 16;" :: "r"(dst), "l"(src));
}
__device__ __forceinline__ void cp_commit() {
    asm volatile("cp.async.commit_group;");
}
template<int N> __device__ __forceinline__ void cp_wait() {
    asm volatile("cp.async.wait_group %0;" :: "n"(N));
}
// split fp32 quad -> packed bf16 hi pair + lo pair
__device__ __forceinline__ void split4(float4 v, uint2& hh, uint2& ll) {
    bf16 hx = __float2bfloat16(v.x), hy = __float2bfloat16(v.y);
    bf16 hz = __float2bfloat16(v.z), hw = __float2bfloat16(v.w);
    float lx = v.x - __bfloat162float(hx), ly = v.y - __bfloat162float(hy);
    float lz = v.z - __bfloat162float(hz), lw = v.w - __bfloat162float(hw);
    __nv_bfloat162 h0 = {hx, hy}, h1 = {hz, hw};
    __nv_bfloat162 l0 = __floats2bfloat162_rn(lx, ly);
    __nv_bfloat162 l1 = __floats2bfloat162_rn(lz, lw);
    hh.x = *reinterpret_cast<uint32_t*>(&h0); hh.y = *reinterpret_cast<uint32_t*>(&h1);
    ll.x = *reinterpret_cast<uint32_t*>(&l0); ll.y = *reinterpret_cast<uint32_t*>(&l1);
}

// ===========================================================================
// Batched NT GEMM on presplit bf16 hi/lo operands (3-term compensated):
//   C[z](MxN) = A[z](MxK) @ B[z](NxK)^T, all K-major
// epilogue: +bias(col), *1/max(rnorm(row),eps), optional row-sumsq atomics,
//           output to fp32 (Cf) and/or split bf16 (Ch/Cl)
// BM=128, BK=64, 512 threads, double-buffered cp.async
// ===========================================================================
template<int BN>
__global__ void __launch_bounds__(512, 1)
gemm_ps(const bf16* __restrict__ Ah_, const bf16* __restrict__ Al_,
        const bf16* __restrict__ Bh_, const bf16* __restrict__ Bl_,
        const float* __restrict__ bias, const float* __restrict__ rnorm,
        float* __restrict__ nrmsq,
        float* __restrict__ Cf, bf16* __restrict__ Ch, bf16* __restrict__ Cl,
        int K, int H,
        long lda, long ldb, long ldc,
        long sAb, long sAh, long sBb, long sBh, long sCb, long sCh,
        long sNz)
{
    constexpr int BM = 128, BK = 64;
    constexpr int PA = 72;                      // smem row pitch (bf16)
    constexpr int NI = BN / 32;
    constexpr int SBUF = (2 * BM + 2 * BN) * PA; // bf16 elems per buffer
    constexpr int OAh = 0, OAl = BM * PA, OBh = 2 * BM * PA, OBl = 2 * BM * PA + BN * PA;
    constexpr int AIT = (BM * 8 * 2) / 512;     // 4 chunks/thread for A hi+lo
    constexpr int BIT = (BN * 8 * 2) / 512;     // 4 or 2 for B
    constexpr int SP = BN + 4;

    extern __shared__ char smem_raw[];
    bf16* sm = (bf16*)smem_raw;
    float* stg = (float*)smem_raw;
    uint32_t smbase = smem_u32(smem_raw);

    int tid = threadIdx.x, wid = tid >> 5, lane = tid & 31;
    int gid = lane >> 2, tig = lane & 3;
    int wm0 = (wid >> 2) * 32, wn0 = (wid & 3) * (BN / 4);

    int z = blockIdx.z, b = z / H, h = z - b * H;
    int row0 = blockIdx.y * BM, col0 = blockIdx.x * BN;
    long offA = (long)b * sAb + (long)h * sAh + (long)row0 * lda;
    long offB = (long)b * sBb + (long)h * sBh + (long)col0 * ldb;
    const bf16* AhP = Ah_ + offA; const bf16* AlP = Al_ + offA;
    const bf16* BhP = Bh_ + offB; const bf16* BlP = Bl_ + offB;
    if (rnorm) rnorm += (long)z * sNz;
    if (nrmsq) nrmsq += (long)z * sNz;

    // per-thread cp.async maps
    const bf16* asrc[AIT]; uint32_t adst[AIT];
#pragma unroll
    for (int i = 0; i < AIT; i++) {
        int idx = tid + i * 512;
        int lo = idx >= BM * 8;
        int w = idx - lo * BM * 8;
        int r = w >> 3, kc = w & 7;
        asrc[i] = (lo ? AlP : AhP) + (long)r * lda + kc * 8;
        adst[i] = smbase + 2u * ((lo ? OAl : OAh) + r * PA + kc * 8);
    }
    const bf16* bsrc[BIT]; uint32_t bdst[BIT];
#pragma unroll
    for (int i = 0; i < BIT; i++) {
        int idx = tid + i * 512;
        int lo = idx >= BN * 8;
        int w = idx - lo * BN * 8;
        int r = w >> 3, kc = w & 7;
        bsrc[i] = (lo ? BlP : BhP) + (long)r * ldb + kc * 8;
        bdst[i] = smbase + 2u * ((lo ? OBl : OBh) + r * PA + kc * 8);
    }

    float acc[2][NI][4];
#pragma unroll
    for (int mi = 0; mi < 2; mi++)
#pragma unroll
        for (int ni = 0; ni < NI; ni++)
#pragma unroll
            for (int j = 0; j < 4; j++) acc[mi][ni][j] = 0.f;

    const int NS = K / BK;

    // prologue: stage 0 -> buffer 0
    {
#pragma unroll
        for (int i = 0; i < AIT; i++) cpa16(adst[i], asrc[i]);
#pragma unroll
        for (int i = 0; i < BIT; i++) cpa16(bdst[i], bsrc[i]);
        cp_commit();
    }

    for (int s = 0; s < NS; s++) {
        if (s + 1 < NS) {
            long ko = (long)(s + 1) * BK;
            uint32_t boff = ((s + 1) & 1) * (uint32_t)(SBUF * 2);
#pragma unroll
            for (int i = 0; i < AIT; i++) cpa16(adst[i] + boff, asrc[i] + ko);
#pragma unroll
            for (int i = 0; i < BIT; i++) cpa16(bdst[i] + boff, bsrc[i] + ko);
            cp_commit();
            cp_wait<1>();
        } else {
            cp_wait<0>();
        }
        __syncthreads();
        const bf16* bb = sm + (s & 1) * SBUF;
#pragma unroll
        for (int k16 = 0; k16 < BK; k16 += 16) {
            uint32_t ah[2][4], al[2][4], bh[NI][2], bl[NI][2];
#pragma unroll
            for (int mi = 0; mi < 2; mi++) {
                int r = wm0 + mi * 16 + gid;
                int c = k16 + tig * 2;
                ah[mi][0] = *(const uint32_t*)(bb + OAh + r * PA + c);
                ah[mi][1] = *(const uint32_t*)(bb + OAh + (r + 8) * PA + c);
                ah[mi][2] = *(const uint32_t*)(bb + OAh + r * PA + c + 8);
                ah[mi][3] = *(const uint32_t*)(bb + OAh + (r + 8) * PA + c + 8);
                al[mi][0] = *(const uint32_t*)(bb + OAl + r * PA + c);
                al[mi][1] = *(const uint32_t*)(bb + OAl + (r + 8) * PA + c);
                al[mi][2] = *(const uint32_t*)(bb + OAl + r * PA + c + 8);
                al[mi][3] = *(const uint32_t*)(bb + OAl + (r + 8) * PA + c + 8);
            }
#pragma unroll
            for (int ni = 0; ni < NI; ni++) {
                int n = wn0 + ni * 8 + gid;
                int c = k16 + tig * 2;
                bh[ni][0] = *(const uint32_t*)(bb + OBh + n * PA + c);
                bh[ni][1] = *(const uint32_t*)(bb + OBh + n * PA + c + 8);
                bl[ni][0] = *(const uint32_t*)(bb + OBl + n * PA + c);
                bl[ni][1] = *(const uint32_t*)(bb + OBl + n * PA + c + 8);
            }
#pragma unroll
            for (int mi = 0; mi < 2; mi++)
#pragma unroll
                for (int ni = 0; ni < NI; ni++) {
                    mma_bf16(acc[mi][ni], ah[mi], bh[ni]);
                    mma_bf16(acc[mi][ni], ah[mi], bl[ni]);
                    mma_bf16(acc[mi][ni], al[mi], bh[ni]);
                }
        }
        __syncthreads();
    }

    // ---- epilogue: regs -> smem staging -> fused epilogue + coalesced STG ----
#pragma unroll
    for (int mi = 0; mi < 2; mi++)
#pragma unroll
        for (int ni = 0; ni < NI; ni++) {
            int r = wm0 + mi * 16 + gid;
            int c = wn0 + ni * 8 + tig * 2;
            stg[r * SP + c]           = acc[mi][ni][0];
            stg[r * SP + c + 1]       = acc[mi][ni][1];
            stg[(r + 8) * SP + c]     = acc[mi][ni][2];
            stg[(r + 8) * SP + c + 1] = acc[mi][ni][3];
        }
    __syncthreads();

    if (nrmsq && tid < BM) {
        float ssum = 0.f;
        const float* p = stg + tid * SP;
#pragma unroll 8
        for (int j = 0; j < BN; j++) { float v = p[j]; ssum += v * v; }
        atomicAdd(&nrmsq[row0 + tid], ssum);
    }
    long coff = (long)b * sCb + (long)h * sCh;
#pragma unroll
    for (int i = 0; i < BN / 16; i++) {
        int idx = tid + i * 512;
        int row = idx / (BN / 4), c4 = (idx % (BN / 4)) * 4;
        float4 v = *(const float4*)(stg + row * SP + c4);
        int col = col0 + c4;
        if (bias) {
            float4 bv = *(const float4*)&bias[col];
            v.x += bv.x; v.y += bv.y; v.z += bv.z; v.w += bv.w;
        }
        if (rnorm) {
            float sc = 1.0f / fmaxf(rnorm[row0 + row], NORM_EPS);
            v.x *= sc; v.y *= sc; v.z *= sc; v.w *= sc;
        }
        long cpos = coff + (long)(row0 + row) * ldc + col;
        if (Cf) *(float4*)&Cf[cpos] = v;
        if (Ch) {
            uint2 hh, ll;
            split4(v, hh, ll);
            *(uint2*)&Ch[cpos] = hh;
            *(uint2*)&Cl[cpos] = ll;
        }
    }
}

// ===========================================================================
// elementwise split: fp32 -> bf16 hi/lo
// ===========================================================================
__global__ void split_k(const float* __restrict__ x, bf16* __restrict__ h,
                        bf16* __restrict__ l, long n4)
{
    long i = (long)blockIdx.x * 256 + threadIdx.x;
    if (i >= n4) return;
    float4 v = *(const float4*)&x[i * 4];
    uint2 hh, ll;
    split4(v, hh, ll);
    *(uint2*)&h[i * 4] = hh;
    *(uint2*)&l[i * 4] = ll;
}

// ===========================================================================
// tiled transpose + split: out[x][y] = split(in[y][x])
// ===========================================================================
__global__ void transpose_split_k(const float* __restrict__ in,
                                  bf16* __restrict__ oh, bf16* __restrict__ ol,
                                  long ldi, long ldo, int H,
                                  long sIb, long sIh, long sOz)
{
    __shared__ float t[32][33];
    int z = blockIdx.z, b = z / H, h = z - b * H;
    in += (long)b * sIb + (long)h * sIh;
    oh += (long)z * sOz; ol += (long)z * sOz;
    int x0 = blockIdx.x * 32, y0 = blockIdx.y * 32;
    int tx = threadIdx.x & 31, ty = threadIdx.x >> 5;
#pragma unroll
    for (int i = 0; i < 4; i++)
        t[ty + i * 8][tx] = in[(long)(y0 + ty + i * 8) * ldi + x0 + tx];
    __syncthreads();
#pragma unroll
    for (int i = 0; i < 4; i++) {
        float v = t[tx][ty + i * 8];
        bf16 hv = __float2bfloat16(v);
        long o = (long)(x0 + ty + i * 8) * ldo + y0 + tx;
        oh[o] = hv;
        ol[o] = __float2bfloat16(v - __bfloat162float(hv));
    }
}

// ===========================================================================
// LayerNorm (fp32 in, split bf16 out)
// ===========================================================================
__global__ void layernorm_split_k(const float* __restrict__ Z,
                                  bf16* __restrict__ oh, bf16* __restrict__ ol,
                                  const float* __restrict__ g, const float* __restrict__ be)
{
    __shared__ float red[256];
    int tid = threadIdx.x;
    const float* row = Z + (long)blockIdx.x * DL;
    float v[4];
#pragma unroll
    for (int t = 0; t < 4; t++) v[t] = row[tid + t * 256];
    float s = v[0] + v[1] + v[2] + v[3];
    red[tid] = s; __syncthreads();
    for (int off = 128; off > 0; off >>= 1) {
        if (tid < off) red[tid] += red[tid + off];
        __syncthreads();
    }
    float mu = red[0] * (1.0f / DL);
    __syncthreads();
    float vs = 0.f;
#pragma unroll
    for (int t = 0; t < 4; t++) { float d = v[t] - mu; vs += d * d; }
    red[tid] = vs; __syncthreads();
    for (int off = 128; off > 0; off >>= 1) {
        if (tid < off) red[tid] += red[tid + off];
        __syncthreads();
    }
    float rstd = rsqrtf(red[0] * (1.0f / DL) + LN_EPS);
    long base = (long)blockIdx.x * DL;
#pragma unroll
    for (int t = 0; t < 4; t++) {
        int i = tid + t * 256;
        float o = (v[t] - mu) * rstd * g[i] + be[i];
        bf16 hv = __float2bfloat16(o);
        oh[base + i] = hv;
        ol[base + i] = __float2bfloat16(o - __bfloat162float(hv));
    }
}

// ===========================================================================
// Phasor: phi = q_row @ Wphi + bphi ; out = split([q*cos(phi) | q*sin(phi)])
// ===========================================================================
__global__ void phasor_split_k(const float* __restrict__ Qin,
                               bf16* __restrict__ oh, bf16* __restrict__ ol,
                               const float* __restrict__ Wphi, const float* __restrict__ bphi)
{
    __shared__ float W[HD][HD];
    __shared__ float qrow[4][HD + 4];
    int tid = threadIdx.x;
    int j = tid & 63, g = tid >> 6;
    for (int i = tid; i < HD * HD; i += 256) W[i >> 6][i & 63] = Wphi[i];
    __syncthreads();
    const float* base = Qin + (long)blockIdx.x * (NH * HD);
    long obase = (long)blockIdx.x * (NH * 2 * HD);
    float bj = bphi[j];
    for (int hb = 0; hb < NH; hb += 4) {
        int h = hb + g;
        qrow[g][j] = base[h * HD + j];
        __syncthreads();
        float phi = bj;
#pragma unroll 16
        for (int d = 0; d < HD; d++) phi += qrow[g][d] * W[d][j];
        float q = qrow[g][j];
        float sp, cp;
        sincosf(phi, &sp, &cp);
        float vc = q * cp, vsn = q * sp;
        bf16 hc = __float2bfloat16(vc), hs = __float2bfloat16(vsn);
        long oc = obase + h * 2 * HD + j;
        oh[oc] = hc;           ol[oc] = __float2bfloat16(vc - __bfloat162float(hc));
        oh[oc + HD] = hs;      ol[oc + HD] = __float2bfloat16(vsn - __bfloat162float(hs));
        __syncthreads();
    }
}

__global__ void sqrt_k(float* __restrict__ p, int n)
{
    int i = blockIdx.x * 256 + threadIdx.x;
    if (i < n) p[i] = sqrtf(p[i]);
}

// ===========================================================================
extern "C" void kernel_launch(void* const* d_in, const int* in_sizes, int n_in,
                              void* d_out, int out_size)
{
    const float* query = (const float*)d_in[0];
    const float* Wz   = (const float*)d_in[3];
    const float* bz   = (const float*)d_in[4];
    const float* ln_g = (const float*)d_in[5];
    const float* ln_b = (const float*)d_in[6];
    const float* Wq   = (const float*)d_in[7];
    const float* bq   = (const float*)d_in[8];
    const float* Wr   = (const float*)d_in[9];
    const float* br   = (const float*)d_in[10];
    const float* Wh   = (const float*)d_in[11];
    const float* bh   = (const float*)d_in[12];
    const float* Wphi = (const float*)d_in[13];
    const float* bphi = (const float*)d_in[14];
    const float* Wo   = (const float*)d_in[15];
    const float* bo   = (const float*)d_in[16];
    float* out = (float*)d_out;

    bf16 *Qs_h, *Qs_l, *WT_h, *WT_l, *Zs_h, *Zs_l, *Qc_h, *Qc_l, *Rc_h, *Rc_l;
    bf16 *Sc_h, *Sc_l, *HvT_h, *HvT_l, *Ao_h, *Ao_l;
    float *Z, *Q, *R, *Hh, *Nm;
    cudaGetSymbolAddress((void**)&Qs_h, g_Qs_h); cudaGetSymbolAddress((void**)&Qs_l, g_Qs_l);
    cudaGetSymbolAddress((void**)&WT_h, g_WT_h); cudaGetSymbolAddress((void**)&WT_l, g_WT_l);
    cudaGetSymbolAddress((void**)&Z,    g_Z);
    cudaGetSymbolAddress((void**)&Zs_h, g_Zs_h); cudaGetSymbolAddress((void**)&Zs_l, g_Zs_l);
    cudaGetSymbolAddress((void**)&Q,    g_Q);
    cudaGetSymbolAddress((void**)&R,    g_R);
    cudaGetSymbolAddress((void**)&Hh,   g_H);
    cudaGetSymbolAddress((void**)&Qc_h, g_Qc_h); cudaGetSymbolAddress((void**)&Qc_l, g_Qc_l);
    cudaGetSymbolAddress((void**)&Rc_h, g_Rc_h); cudaGetSymbolAddress((void**)&Rc_l, g_Rc_l);
    cudaGetSymbolAddress((void**)&Sc_h, g_Sc_h); cudaGetSymbolAddress((void**)&Sc_l, g_Sc_l);
    cudaGetSymbolAddress((void**)&Nm,   g_Nrm);
    cudaGetSymbolAddress((void**)&HvT_h, g_HvT_h); cudaGetSymbolAddress((void**)&HvT_l, g_HvT_l);
    cudaGetSymbolAddress((void**)&Ao_h, g_Ao_h); cudaGetSymbolAddress((void**)&Ao_l, g_Ao_l);

    // dynamic smem sizes: max(double k-buffers, staging)
    const int SM128 = (2 * 128 + 2 * 128) * 72 * 2 * 2;     // 147,456
    const int SM64k = (2 * 128 + 2 * 64) * 72 * 2 * 2;      // 110,592
    const int SM64s = 128 * (64 + 4) * 4;                   // 34,816
    const int SM64 = SM64k > SM64s ? SM64k : SM64s;
    cudaFuncSetAttribute(gemm_ps<128>, cudaFuncAttributeMaxDynamicSharedMemorySize, SM128);
    cudaFuncSetAttribute(gemm_ps<64>,  cudaFuncAttributeMaxDynamicSharedMemorySize, SM64);

    dim3 blk(256), gblk(512);
    long szW = (long)DM * DL;
    bf16* WzT_h = WT_h + 0 * szW; bf16* WzT_l = WT_l + 0 * szW;
    bf16* WqT_h = WT_h + 1 * szW; bf16* WqT_l = WT_l + 1 * szW;
    bf16* WrT_h = WT_h + 2 * szW; bf16* WrT_l = WT_l + 2 * szW;
    bf16* WhT_h = WT_h + 3 * szW; bf16* WhT_l = WT_l + 3 * szW;
    bf16* WoT_h = WT_h + 4 * szW; bf16* WoT_l = WT_l + 4 * szW;

    // 0) transpose+split weights; split query
    transpose_split_k<<<dim3(32, 32, 1), blk>>>(Wz, WzT_h, WzT_l, DL, DM, 1, 0, 0, 0);
    transpose_split_k<<<dim3(32, 32, 1), blk>>>(Wq, WqT_h, WqT_l, DM, DL, 1, 0, 0, 0);
    transpose_split_k<<<dim3(32, 32, 1), blk>>>(Wr, WrT_h, WrT_l, DM, DL, 1, 0, 0, 0);
    transpose_split_k<<<dim3(32, 32, 1), blk>>>(Wh, WhT_h, WhT_l, DM, DL, 1, 0, 0, 0);
    transpose_split_k<<<dim3(32, 32, 1), blk>>>(Wo, WoT_h, WoT_l, DM, DM, 1, 0, 0, 0);
    split_k<<<(TOK * DM / 4 + 255) / 256, blk>>>(query, Qs_h, Qs_l, (long)TOK * DM / 4);

    // 1) Z = query @ Wz + bz  (fp32 out, LN consumes)
    gemm_ps<128><<<dim3(DL / 128, TOK / 128, 1), gblk, SM128>>>(
        Qs_h, Qs_l, WzT_h, WzT_l, bz, nullptr, nullptr, Z, nullptr, nullptr,
        DM, 1, DM, DM, DL, 0, 0, 0, 0, 0, 0, 0);

    // 2) LayerNorm -> split Zs
    layernorm_split_k<<<TOK, blk>>>(Z, Zs_h, Zs_l, ln_g, ln_b);

    // 3) Q/R/H projections (fp32 out; phasor/transpose consume)
    gemm_ps<128><<<dim3(DM / 128, TOK / 128, 1), gblk, SM128>>>(
        Zs_h, Zs_l, WqT_h, WqT_l, bq, nullptr, nullptr, Q, nullptr, nullptr,
        DL, 1, DL, DL, DM, 0, 0, 0, 0, 0, 0, 0);
    gemm_ps<128><<<dim3(DM / 128, TOK / 128, 1), gblk, SM128>>>(
        Zs_h, Zs_l, WrT_h, WrT_l, br, nullptr, nullptr, R, nullptr, nullptr,
        DL, 1, DL, DL, DM, 0, 0, 0, 0, 0, 0, 0);
    gemm_ps<128><<<dim3(DM / 128, TOK / 128, 1), gblk, SM128>>>(
        Zs_h, Zs_l, WhT_h, WhT_l, bh, nullptr, nullptr, Hh, nullptr, nullptr,
        DL, 1, DL, DL, DM, 0, 0, 0, 0, 0, 0, 0);

    // 4) phasor -> split Qc, Rc
    phasor_split_k<<<TOK, blk>>>(Q, Qc_h, Qc_l, Wphi, bphi);
    phasor_split_k<<<TOK, blk>>>(R, Rc_h, Rc_l, Wphi, bphi);

    // 5) Hv^T per (b,h) with split
    transpose_split_k<<<dim3(HD / 32, Sv / 32, Bv * NH), blk>>>(
        Hh, HvT_h, HvT_l, DM, Sv, NH, (long)Sv * DM, HD, (long)HD * Sv);

    // 6) zero sumsq accumulator
    cudaMemsetAsync(Nm, 0, (size_t)Bv * NH * Sv * sizeof(float));

    // 7) scores = Qc @ Rc^T -> split Sc, fused row-sumsq atomics
    gemm_ps<128><<<dim3(Sv / 128, Sv / 128, Bv * NH), gblk, SM128>>>(
        Qc_h, Qc_l, Rc_h, Rc_l, nullptr, nullptr, Nm, nullptr, Sc_h, Sc_l,
        2 * HD, NH,
        NH * 2 * HD, NH * 2 * HD, Sv,
        (long)Sv * NH * 2 * HD, 2 * HD,
        (long)Sv * NH * 2 * HD, 2 * HD,
        (long)NH * Sv * Sv, (long)Sv * Sv,
        Sv);

    // 8) norm = sqrt(sumsq)
    sqrt_k<<<(Bv * NH * Sv + 255) / 256, blk>>>(Nm, Bv * NH * Sv);

    // 9) attn_out = (scores/norm) @ Hv -> split Ao
    gemm_ps<64><<<dim3(1, Sv / 128, Bv * NH), gblk, SM64>>>(
        Sc_h, Sc_l, HvT_h, HvT_l, nullptr, Nm, nullptr, nullptr, Ao_h, Ao_l,
        Sv, NH,
        Sv, Sv, DM,
        (long)NH * Sv * Sv, (long)Sv * Sv,
        (long)NH * HD * Sv, (long)HD * Sv,
        (long)Sv * DM, HD,
        Sv);

    // 10) out = attn_out @ Wo + bo
    gemm_ps<128><<<dim3(DM / 128, TOK / 128, 1), gblk, SM128>>>(
        Ao_h, Ao_l, WoT_h, WoT_l, bo, nullptr, nullptr, out, nullptr, nullptr,
        DM, 1, DM, DM, DM, 0, 0, 0, 0, 0, 0, 0);
}

// round 5
// speedup vs baseline: 2.8928x; 1.1595x over previous
#include <cuda_runtime.h>
#include <cuda_bf16.h>
#include <math.h>
#include <stdint.h>

typedef __nv_bfloat16 bf16;

#define Bv 2
#define Sv 2048
#define DM 1024
#define NH 16
#define HD 64
#define DL 1024
#define TOK (Bv*Sv)          // 4096
#define LN_EPS 1e-5f
#define NORM_EPS 1e-12f

// ---- scratch (static device globals; allocation-free) ----
__device__ bf16  g_Qs_h[(size_t)TOK * DM],  g_Qs_l[(size_t)TOK * DM];
__device__ bf16  g_WT_h[5 * (size_t)DM * DL], g_WT_l[5 * (size_t)DM * DL];
__device__ float g_Z   [(size_t)TOK * DL];
__device__ bf16  g_Zs_h[(size_t)TOK * DL],  g_Zs_l[(size_t)TOK * DL];
__device__ float g_QRH [(size_t)TOK * 3 * DM];          // Q|R|H fused output
__device__ float g_bqrh[3 * DM];
__device__ bf16  g_Qc_h[(size_t)TOK * NH * 2 * HD], g_Qc_l[(size_t)TOK * NH * 2 * HD];
__device__ bf16  g_Rc_h[(size_t)TOK * NH * 2 * HD], g_Rc_l[(size_t)TOK * NH * 2 * HD];
__device__ bf16  g_HvT_h[(size_t)Bv * NH * HD * Sv], g_HvT_l[(size_t)Bv * NH * HD * Sv];
__device__ bf16  g_Ao_h[(size_t)TOK * DM], g_Ao_l[(size_t)TOK * DM];

// ===========================================================================
// helpers
// ===========================================================================
__device__ __forceinline__ uint32_t smem_u32(const void* p) {
    uint32_t a;
    asm("{ .reg .u64 t; cvta.to.shared.u64 t, %1; cvt.u32.u64 %0, t; }"
        : "=r"(a) : "l"(p));
    return a;
}
__device__ __forceinline__ void mma_bf16(float* d, const uint32_t* a, const uint32_t* b) {
    asm volatile(
        "mma.sync.aligned.m16n8k16.row.col.f32.bf16.bf16.f32 "
        "{%0,%1,%2,%3}, {%4,%5,%6,%7}, {%8,%9}, {%0,%1,%2,%3};"
        : "+f"(d[0]), "+f"(d[1]), "+f"(d[2]), "+f"(d[3])
        : "r"(a[0]), "r"(a[1]), "r"(a[2]), "r"(a[3]), "r"(b[0]), "r"(b[1]));
}
__device__ __forceinline__ void cpa16(uint32_t dst, const void* src) {
    asm volatile("cp.async.cg.shared.global [%0], [%1], 16;" :: "r"(dst), "l"(src));
}
__device__ __forceinline__ void cp_commit() { asm volatile("cp.async.commit_group;"); }
template<int N> __device__ __forceinline__ void cp_wait() {
    asm volatile("cp.async.wait_group %0;" :: "n"(N));
}
__device__ __forceinline__ uint32_t packhi2(float a, float b) {
    __nv_bfloat162 t = __floats2bfloat162_rn(a, b);
    return *reinterpret_cast<uint32_t*>(&t);
}
__device__ __forceinline__ void split4(float4 v, uint2& hh, uint2& ll) {
    bf16 hx = __float2bfloat16(v.x), hy = __float2bfloat16(v.y);
    bf16 hz = __float2bfloat16(v.z), hw = __float2bfloat16(v.w);
    float lx = v.x - __bfloat162float(hx), ly = v.y - __bfloat162float(hy);
    float lz = v.z - __bfloat162float(hz), lw = v.w - __bfloat162float(hw);
    __nv_bfloat162 h0 = {hx, hy}, h1 = {hz, hw};
    hh.x = *reinterpret_cast<uint32_t*>(&h0); hh.y = *reinterpret_cast<uint32_t*>(&h1);
    ll.x = packhi2(lx, ly); ll.y = packhi2(lz, lw);
}
// split 2 floats -> (hi-pair, lo-pair)
__device__ __forceinline__ void split2(float a, float b, uint32_t& hp, uint32_t& lp) {
    bf16 ha = __float2bfloat16(a), hb = __float2bfloat16(b);
    hp = packhi2(__bfloat162float(ha), __bfloat162float(hb));   // exact re-pack
    lp = packhi2(a - __bfloat162float(ha), b - __bfloat162float(hb));
}

// ===========================================================================
// Batched NT GEMM on presplit bf16 hi/lo operands (3-term compensated)
// BM=128, BN=128, BK=64, 512 threads, double-buffered cp.async
// ===========================================================================
__global__ void __launch_bounds__(512, 1)
gemm_ps(const bf16* __restrict__ Ah_, const bf16* __restrict__ Al_,
        const bf16* __restrict__ Bh_, const bf16* __restrict__ Bl_,
        const float* __restrict__ bias, float* __restrict__ Cf,
        int K, long lda, long ldb, long ldc)
{
    constexpr int BM = 128, BN = 128, BK = 64;
    constexpr int PA = 72;
    constexpr int NI = 4;
    constexpr int SBUF = (2 * BM + 2 * BN) * PA;
    constexpr int OAh = 0, OAl = BM * PA, OBh = 2 * BM * PA, OBl = 2 * BM * PA + BN * PA;
    constexpr int AIT = 4, BIT = 4;
    constexpr int SP = BN + 4;

    extern __shared__ char smem_raw[];
    bf16* sm = (bf16*)smem_raw;
    float* stg = (float*)smem_raw;
    uint32_t smbase = smem_u32(smem_raw);

    int tid = threadIdx.x, wid = tid >> 5, lane = tid & 31;
    int gid = lane >> 2, tig = lane & 3;
    int wm0 = (wid >> 2) * 32, wn0 = (wid & 3) * 32;

    int row0 = blockIdx.y * BM, col0 = blockIdx.x * BN;
    const bf16* AhP = Ah_ + (long)row0 * lda;
    const bf16* AlP = Al_ + (long)row0 * lda;
    const bf16* BhP = Bh_ + (long)col0 * ldb;
    const bf16* BlP = Bl_ + (long)col0 * ldb;

    const bf16* asrc[AIT]; uint32_t adst[AIT];
#pragma unroll
    for (int i = 0; i < AIT; i++) {
        int idx = tid + i * 512;
        int lo = idx >= BM * 8;
        int w = idx - lo * BM * 8;
        int r = w >> 3, kc = w & 7;
        asrc[i] = (lo ? AlP : AhP) + (long)r * lda + kc * 8;
        adst[i] = smbase + 2u * ((lo ? OAl : OAh) + r * PA + kc * 8);
    }
    const bf16* bsrc[BIT]; uint32_t bdst[BIT];
#pragma unroll
    for (int i = 0; i < BIT; i++) {
        int idx = tid + i * 512;
        int lo = idx >= BN * 8;
        int w = idx - lo * BN * 8;
        int r = w >> 3, kc = w & 7;
        bsrc[i] = (lo ? BlP : BhP) + (long)r * ldb + kc * 8;
        bdst[i] = smbase + 2u * ((lo ? OBl : OBh) + r * PA + kc * 8);
    }

    float acc[2][NI][4];
#pragma unroll
    for (int mi = 0; mi < 2; mi++)
#pragma unroll
        for (int ni = 0; ni < NI; ni++)
#pragma unroll
            for (int j = 0; j < 4; j++) acc[mi][ni][j] = 0.f;

    const int NS = K / BK;
    {
#pragma unroll
        for (int i = 0; i < AIT; i++) cpa16(adst[i], asrc[i]);
#pragma unroll
        for (int i = 0; i < BIT; i++) cpa16(bdst[i], bsrc[i]);
        cp_commit();
    }
    for (int s = 0; s < NS; s++) {
        if (s + 1 < NS) {
            long ko = (long)(s + 1) * BK;
            uint32_t boff = ((s + 1) & 1) * (uint32_t)(SBUF * 2);
#pragma unroll
            for (int i = 0; i < AIT; i++) cpa16(adst[i] + boff, asrc[i] + ko);
#pragma unroll
            for (int i = 0; i < BIT; i++) cpa16(bdst[i] + boff, bsrc[i] + ko);
            cp_commit();
            cp_wait<1>();
        } else {
            cp_wait<0>();
        }
        __syncthreads();
        const bf16* bb = sm + (s & 1) * SBUF;
#pragma unroll
        for (int k16 = 0; k16 < BK; k16 += 16) {
            uint32_t ah[2][4], al[2][4], bh[NI][2], bl[NI][2];
#pragma unroll
            for (int mi = 0; mi < 2; mi++) {
                int r = wm0 + mi * 16 + gid;
                int c = k16 + tig * 2;
                ah[mi][0] = *(const uint32_t*)(bb + OAh + r * PA + c);
                ah[mi][1] = *(const uint32_t*)(bb + OAh + (r + 8) * PA + c);
                ah[mi][2] = *(const uint32_t*)(bb + OAh + r * PA + c + 8);
                ah[mi][3] = *(const uint32_t*)(bb + OAh + (r + 8) * PA + c + 8);
                al[mi][0] = *(const uint32_t*)(bb + OAl + r * PA + c);
                al[mi][1] = *(const uint32_t*)(bb + OAl + (r + 8) * PA + c);
                al[mi][2] = *(const uint32_t*)(bb + OAl + r * PA + c + 8);
                al[mi][3] = *(const uint32_t*)(bb + OAl + (r + 8) * PA + c + 8);
            }
#pragma unroll
            for (int ni = 0; ni < NI; ni++) {
                int n = wn0 + ni * 8 + gid;
                int c = k16 + tig * 2;
                bh[ni][0] = *(const uint32_t*)(bb + OBh + n * PA + c);
                bh[ni][1] = *(const uint32_t*)(bb + OBh + n * PA + c + 8);
                bl[ni][0] = *(const uint32_t*)(bb + OBl + n * PA + c);
                bl[ni][1] = *(const uint32_t*)(bb + OBl + n * PA + c + 8);
            }
#pragma unroll
            for (int mi = 0; mi < 2; mi++)
#pragma unroll
                for (int ni = 0; ni < NI; ni++) {
                    mma_bf16(acc[mi][ni], ah[mi], bh[ni]);
                    mma_bf16(acc[mi][ni], ah[mi], bl[ni]);
                    mma_bf16(acc[mi][ni], al[mi], bh[ni]);
                }
        }
        __syncthreads();
    }

#pragma unroll
    for (int mi = 0; mi < 2; mi++)
#pragma unroll
        for (int ni = 0; ni < NI; ni++) {
            int r = wm0 + mi * 16 + gid;
            int c = wn0 + ni * 8 + tig * 2;
            stg[r * SP + c]           = acc[mi][ni][0];
            stg[r * SP + c + 1]       = acc[mi][ni][1];
            stg[(r + 8) * SP + c]     = acc[mi][ni][2];
            stg[(r + 8) * SP + c + 1] = acc[mi][ni][3];
        }
    __syncthreads();
#pragma unroll
    for (int i = 0; i < 8; i++) {
        int idx = tid + i * 512;
        int row = idx >> 5, c4 = (idx & 31) * 4;
        float4 v = *(const float4*)(stg + row * SP + c4);
        int col = col0 + c4;
        if (bias) {
            float4 bv = *(const float4*)&bias[col];
            v.x += bv.x; v.y += bv.y; v.z += bv.z; v.w += bv.w;
        }
        *(float4*)&Cf[(long)(row0 + row) * ldc + col] = v;
    }
}

// ===========================================================================
// Fused attention: per (b,h,q-tile 64): S = Qc@Rc^T (regs), sumsq, U += S@Hv,
// then U / max(||row||,eps) -> Ao split. 256 threads, 8 warps (2m x 4n).
// ===========================================================================
#define NT 32            // r-tiles of 64
#define PQ 136           // Qc/Rc smem pitch (bf16), K=128
#define PH 72            // Hv smem pitch, K-slice=64
#define STG_E 26624      // bf16 elems per stage: Rc 2*64*136 + Hv 2*64*72
#define ORH 0
#define ORL (64*PQ)
#define OHH (2*64*PQ)
#define OHL (2*64*PQ + 64*PH)
#define OQH (2*STG_E)
#define OQL (2*STG_E + 64*PQ)
#define FA_SMEM ((2*STG_E + 2*64*PQ) * 2)   // 141,312 bytes

__global__ void __launch_bounds__(256, 1)
fused_attn_k(const bf16* __restrict__ Qch, const bf16* __restrict__ Qcl,
             const bf16* __restrict__ Rch, const bf16* __restrict__ Rcl,
             const bf16* __restrict__ Hth, const bf16* __restrict__ Htl,
             bf16* __restrict__ Aoh, bf16* __restrict__ Aol)
{
    extern __shared__ char smem_raw[];
    bf16* sm = (bf16*)smem_raw;
    uint32_t smbase = smem_u32(smem_raw);

    int tid = threadIdx.x, wid = tid >> 5, lane = tid & 31;
    int gid = lane >> 2, tig = lane & 3;
    int mw = wid >> 2, nw = wid & 3;     // 2 m-warps x 4 n-warps

    int qt = blockIdx.x, z = blockIdx.z;
    int b = z >> 4, h = z & 15;
    int row0 = qt * 64;
    long qtok = ((long)(b * Sv + row0)) * (NH * 2 * HD) + h * 128;
    long zHv = (long)z * HD * Sv;

    // ---- Qc prologue loads (8 chunks/thread) ----
#pragma unroll
    for (int i = 0; i < 8; i++) {
        int idx = tid + i * 256;
        int comp = idx >> 10;            // 0 hi, 1 lo
        int w = idx & 1023;
        int r = w >> 4, kc = w & 15;
        const bf16* src = (comp ? Qcl : Qch) + qtok + (long)r * 2048 + kc * 8;
        uint32_t dst = smbase + 2u * ((comp ? OQL : OQH) + r * PQ + kc * 8);
        cpa16(dst, src);
    }
    // ---- stage 0 loads ----
    {
        long rtok = ((long)(b * Sv)) * 2048 + h * 128;
#pragma unroll
        for (int i = 0; i < 8; i++) {
            int idx = tid + i * 256;
            int comp = idx >> 10;
            int w = idx & 1023;
            int r = w >> 4, kc = w & 15;
            const bf16* src = (comp ? Rcl : Rch) + rtok + (long)r * 2048 + kc * 8;
            cpa16(smbase + 2u * ((comp ? ORL : ORH) + r * PQ + kc * 8), src);
        }
#pragma unroll
        for (int i = 0; i < 4; i++) {
            int idx = tid + i * 256;
            int comp = idx >> 9;
            int w = idx & 511;
            int n = w >> 3, kc = w & 7;
            const bf16* src = (comp ? Htl : Hth) + zHv + (long)n * 2048 + kc * 8;
            cpa16(smbase + 2u * ((comp ? OHL : OHH) + n * PH + kc * 8), src);
        }
        cp_commit();
    }

    float U[2][8][4];
#pragma unroll
    for (int mi = 0; mi < 2; mi++)
#pragma unroll
        for (int ni = 0; ni < 8; ni++)
#pragma unroll
            for (int j = 0; j < 4; j++) U[mi][ni][j] = 0.f;
    float sqacc[2][2] = {{0.f, 0.f}, {0.f, 0.f}};

    for (int t = 0; t < NT; t++) {
        if (t + 1 < NT) {
            uint32_t boff = ((t + 1) & 1) * (uint32_t)(STG_E * 2);
            long rtok = ((long)(b * Sv + (t + 1) * 64)) * 2048 + h * 128;
            long hoff = zHv + (t + 1) * 64;
#pragma unroll
            for (int i = 0; i < 8; i++) {
                int idx = tid + i * 256;
                int comp = idx >> 10;
                int w = idx & 1023;
                int r = w >> 4, kc = w & 15;
                const bf16* src = (comp ? Rcl : Rch) + rtok + (long)r * 2048 + kc * 8;
                cpa16(smbase + boff + 2u * ((comp ? ORL : ORH) + r * PQ + kc * 8), src);
            }
#pragma unroll
            for (int i = 0; i < 4; i++) {
                int idx = tid + i * 256;
                int comp = idx >> 9;
                int w = idx & 511;
                int n = w >> 3, kc = w & 7;
                const bf16* src = (comp ? Htl : Hth) + hoff + (long)n * 2048 + kc * 8;
                cpa16(smbase + boff + 2u * ((comp ? OHL : OHH) + n * PH + kc * 8), src);
            }
            cp_commit();
            cp_wait<1>();
        } else {
            cp_wait<0>();
        }
        __syncthreads();
        const bf16* st = sm + (t & 1) * STG_E;

        // ---- Phase A: S tile (64 q x 64 r); warp: rows mw*32..+32, cols nw*16..+16
        float sacc[2][2][4];
#pragma unroll
        for (int mi = 0; mi < 2; mi++)
#pragma unroll
            for (int ni = 0; ni < 2; ni++)
#pragma unroll
                for (int j = 0; j < 4; j++) sacc[mi][ni][j] = 0.f;
#pragma unroll
        for (int k16 = 0; k16 < 128; k16 += 16) {
            uint32_t ah[2][4], al[2][4], bh[2][2], bl[2][2];
            int c = k16 + tig * 2;
#pragma unroll
            for (int mi = 0; mi < 2; mi++) {
                int r = mw * 32 + mi * 16 + gid;
                ah[mi][0] = *(const uint32_t*)(sm + OQH + r * PQ + c);
                ah[mi][1] = *(const uint32_t*)(sm + OQH + (r + 8) * PQ + c);
                ah[mi][2] = *(const uint32_t*)(sm + OQH + r * PQ + c + 8);
                ah[mi][3] = *(const uint32_t*)(sm + OQH + (r + 8) * PQ + c + 8);
                al[mi][0] = *(const uint32_t*)(sm + OQL + r * PQ + c);
                al[mi][1] = *(const uint32_t*)(sm + OQL + (r + 8) * PQ + c);
                al[mi][2] = *(const uint32_t*)(sm + OQL + r * PQ + c + 8);
                al[mi][3] = *(const uint32_t*)(sm + OQL + (r + 8) * PQ + c + 8);
            }
#pragma unroll
            for (int ni = 0; ni < 2; ni++) {
                int n = nw * 16 + ni * 8 + gid;
                bh[ni][0] = *(const uint32_t*)(st + ORH + n * PQ + c);
                bh[ni][1] = *(const uint32_t*)(st + ORH + n * PQ + c + 8);
                bl[ni][0] = *(const uint32_t*)(st + ORL + n * PQ + c);
                bl[ni][1] = *(const uint32_t*)(st + ORL + n * PQ + c + 8);
            }
#pragma unroll
            for (int mi = 0; mi < 2; mi++)
#pragma unroll
                for (int ni = 0; ni < 2; ni++) {
                    mma_bf16(sacc[mi][ni], ah[mi], bh[ni]);
                    mma_bf16(sacc[mi][ni], ah[mi], bl[ni]);
                    mma_bf16(sacc[mi][ni], al[mi], bh[ni]);
                }
        }
        // ---- sumsq accumulate ----
#pragma unroll
        for (int mi = 0; mi < 2; mi++) {
            float s0 = 0.f, s1 = 0.f;
#pragma unroll
            for (int ni = 0; ni < 2; ni++) {
                s0 += sacc[mi][ni][0] * sacc[mi][ni][0] + sacc[mi][ni][1] * sacc[mi][ni][1];
                s1 += sacc[mi][ni][2] * sacc[mi][ni][2] + sacc[mi][ni][3] * sacc[mi][ni][3];
            }
            sqacc[mi][0] += s0; sqacc[mi][1] += s1;
        }
        // ---- Phase B: U += S(bf split) @ Hv-slice; warp k-slice = its 16 S-cols
        uint32_t a2h[2][4], a2l[2][4];
#pragma unroll
        for (int mi = 0; mi < 2; mi++) {
            split2(sacc[mi][0][0], sacc[mi][0][1], a2h[mi][0], a2l[mi][0]);
            split2(sacc[mi][0][2], sacc[mi][0][3], a2h[mi][1], a2l[mi][1]);
            split2(sacc[mi][1][0], sacc[mi][1][1], a2h[mi][2], a2l[mi][2]);
            split2(sacc[mi][1][2], sacc[mi][1][3], a2h[mi][3], a2l[mi][3]);
        }
        int kc2 = nw * 16 + tig * 2;
#pragma unroll
        for (int ni = 0; ni < 8; ni++) {
            uint32_t bh2[2], bl2[2];
            int n = ni * 8 + gid;
            bh2[0] = *(const uint32_t*)(st + OHH + n * PH + kc2);
            bh2[1] = *(const uint32_t*)(st + OHH + n * PH + kc2 + 8);
            bl2[0] = *(const uint32_t*)(st + OHL + n * PH + kc2);
            bl2[1] = *(const uint32_t*)(st + OHL + n * PH + kc2 + 8);
#pragma unroll
            for (int mi = 0; mi < 2; mi++) {
                mma_bf16(U[mi][ni], a2h[mi], bh2);
                mma_bf16(U[mi][ni], a2h[mi], bl2);
                mma_bf16(U[mi][ni], a2l[mi], bh2);
            }
        }
        __syncthreads();
    }

    // ================= epilogue =================
    float* Ured = (float*)smem_raw;            // 64 x 68 fp32 (reuse stage0)
    float* sq = (float*)(smem_raw + 64 * 68 * 4);
    if (tid < 64) sq[tid] = 0.f;
    __syncthreads();
    // sumsq: reduce over tig lanes, then atomic into smem
#pragma unroll
    for (int mi = 0; mi < 2; mi++)
#pragma unroll
        for (int hh = 0; hh < 2; hh++) {
            float v = sqacc[mi][hh];
            v += __shfl_xor_sync(0xFFFFFFFF, v, 1);
            v += __shfl_xor_sync(0xFFFFFFFF, v, 2);
            if (tig == 0) atomicAdd(&sq[mw * 32 + mi * 16 + gid + hh * 8], v);
        }
    __syncthreads();
    if (tid < 64) sq[tid] = 1.0f / fmaxf(sqrtf(sq[tid]), NORM_EPS);
    // U cross-warp reduction (staged, deterministic)
    for (int w = 0; w < 4; w++) {
        if (nw == w) {
#pragma unroll
            for (int mi = 0; mi < 2; mi++)
#pragma unroll
                for (int ni = 0; ni < 8; ni++) {
                    int r = mw * 32 + mi * 16 + gid;
                    int c = ni * 8 + tig * 2;
                    if (w == 0) {
                        Ured[r * 68 + c]           = U[mi][ni][0];
                        Ured[r * 68 + c + 1]       = U[mi][ni][1];
                        Ured[(r + 8) * 68 + c]     = U[mi][ni][2];
                        Ured[(r + 8) * 68 + c + 1] = U[mi][ni][3];
                    } else {
                        Ured[r * 68 + c]           += U[mi][ni][0];
                        Ured[r * 68 + c + 1]       += U[mi][ni][1];
                        Ured[(r + 8) * 68 + c]     += U[mi][ni][2];
                        Ured[(r + 8) * 68 + c + 1] += U[mi][ni][3];
                    }
                }
        }
        __syncthreads();
    }
    // scaled output -> Ao split
#pragma unroll
    for (int i = 0; i < 4; i++) {
        int idx = tid + i * 256;
        int r = idx >> 4, c4 = (idx & 15) * 4;
        float sc = sq[r];
        float4 v = *(const float4*)(Ured + r * 68 + c4);
        v.x *= sc; v.y *= sc; v.z *= sc; v.w *= sc;
        uint2 hh, ll;
        split4(v, hh, ll);
        long gpos = ((long)(b * Sv + row0 + r)) * DM + h * 64 + c4;
        *(uint2*)&Aoh[gpos] = hh;
        *(uint2*)&Aol[gpos] = ll;
    }
}

// ===========================================================================
// small kernels
// ===========================================================================
__global__ void split_k(const float* __restrict__ x, bf16* __restrict__ h,
                        bf16* __restrict__ l, long n4)
{
    long i = (long)blockIdx.x * 256 + threadIdx.x;
    if (i >= n4) return;
    float4 v = *(const float4*)&x[i * 4];
    uint2 hh, ll;
    split4(v, hh, ll);
    *(uint2*)&h[i * 4] = hh;
    *(uint2*)&l[i * 4] = ll;
}

__global__ void transpose_split_k(const float* __restrict__ in,
                                  bf16* __restrict__ oh, bf16* __restrict__ ol,
                                  long ldi, long ldo, int H,
                                  long sIb, long sIh, long sOz)
{
    __shared__ float t[32][33];
    int z = blockIdx.z, b = z / H, h = z - b * H;
    in += (long)b * sIb + (long)h * sIh;
    oh += (long)z * sOz; ol += (long)z * sOz;
    int x0 = blockIdx.x * 32, y0 = blockIdx.y * 32;
    int tx = threadIdx.x & 31, ty = threadIdx.x >> 5;
#pragma unroll
    for (int i = 0; i < 4; i++)
        t[ty + i * 8][tx] = in[(long)(y0 + ty + i * 8) * ldi + x0 + tx];
    __syncthreads();
#pragma unroll
    for (int i = 0; i < 4; i++) {
        float v = t[tx][ty + i * 8];
        bf16 hv = __float2bfloat16(v);
        long o = (long)(x0 + ty + i * 8) * ldo + y0 + tx;
        oh[o] = hv;
        ol[o] = __float2bfloat16(v - __bfloat162float(hv));
    }
}

__global__ void layernorm_split_k(const float* __restrict__ Z,
                                  bf16* __restrict__ oh, bf16* __restrict__ ol,
                                  const float* __restrict__ g, const float* __restrict__ be)
{
    __shared__ float red[256];
    int tid = threadIdx.x;
    const float* row = Z + (long)blockIdx.x * DL;
    float v[4];
#pragma unroll
    for (int t = 0; t < 4; t++) v[t] = row[tid + t * 256];
    float s = v[0] + v[1] + v[2] + v[3];
    red[tid] = s; __syncthreads();
    for (int off = 128; off > 0; off >>= 1) {
        if (tid < off) red[tid] += red[tid + off];
        __syncthreads();
    }
    float mu = red[0] * (1.0f / DL);
    __syncthreads();
    float vs = 0.f;
#pragma unroll
    for (int t = 0; t < 4; t++) { float d = v[t] - mu; vs += d * d; }
    red[tid] = vs; __syncthreads();
    for (int off = 128; off > 0; off >>= 1) {
        if (tid < off) red[tid] += red[tid + off];
        __syncthreads();
    }
    float rstd = rsqrtf(red[0] * (1.0f / DL) + LN_EPS);
    long base = (long)blockIdx.x * DL;
#pragma unroll
    for (int t = 0; t < 4; t++) {
        int i = tid + t * 256;
        float o = (v[t] - mu) * rstd * g[i] + be[i];
        bf16 hv = __float2bfloat16(o);
        oh[base + i] = hv;
        ol[base + i] = __float2bfloat16(o - __bfloat162float(hv));
    }
}

__global__ void phasor_split_k(const float* __restrict__ Qin, long ldq,
                               bf16* __restrict__ oh, bf16* __restrict__ ol,
                               const float* __restrict__ Wphi, const float* __restrict__ bphi)
{
    __shared__ float W[HD][HD];
    __shared__ float qrow[4][HD + 4];
    int tid = threadIdx.x;
    int j = tid & 63, g = tid >> 6;
    for (int i = tid; i < HD * HD; i += 256) W[i >> 6][i & 63] = Wphi[i];
    __syncthreads();
    const float* base = Qin + (long)blockIdx.x * ldq;
    long obase = (long)blockIdx.x * (NH * 2 * HD);
    float bj = bphi[j];
    for (int hb = 0; hb < NH; hb += 4) {
        int h = hb + g;
        qrow[g][j] = base[h * HD + j];
        __syncthreads();
        float phi = bj;
#pragma unroll 16
        for (int d = 0; d < HD; d++) phi += qrow[g][d] * W[d][j];
        float q = qrow[g][j];
        float sp, cp;
        sincosf(phi, &sp, &cp);
        float vc = q * cp, vsn = q * sp;
        bf16 hc = __float2bfloat16(vc), hs = __float2bfloat16(vsn);
        long oc = obase + h * 2 * HD + j;
        oh[oc] = hc;      ol[oc] = __float2bfloat16(vc - __bfloat162float(hc));
        oh[oc + HD] = hs; ol[oc + HD] = __float2bfloat16(vsn - __bfloat162float(hs));
        __syncthreads();
    }
}

__global__ void concat3_k(const float* __restrict__ a, const float* __restrict__ b,
                          const float* __restrict__ c, float* __restrict__ o)
{
    int i = blockIdx.x * 256 + threadIdx.x;
    if (i < DM) o[i] = a[i];
    else if (i < 2 * DM) o[i] = b[i - DM];
    else if (i < 3 * DM) o[i] = c[i - 2 * DM];
}

// ===========================================================================
extern "C" void kernel_launch(void* const* d_in, const int* in_sizes, int n_in,
                              void* d_out, int out_size)
{
    const float* query = (const float*)d_in[0];
    const float* Wz   = (const float*)d_in[3];
    const float* bz   = (const float*)d_in[4];
    const float* ln_g = (const float*)d_in[5];
    const float* ln_b = (const float*)d_in[6];
    const float* Wq   = (const float*)d_in[7];
    const float* bq   = (const float*)d_in[8];
    const float* Wr   = (const float*)d_in[9];
    const float* br   = (const float*)d_in[10];
    const float* Wh   = (const float*)d_in[11];
    const float* bh   = (const float*)d_in[12];
    const float* Wphi = (const float*)d_in[13];
    const float* bphi = (const float*)d_in[14];
    const float* Wo   = (const float*)d_in[15];
    const float* bo   = (const float*)d_in[16];
    float* out = (float*)d_out;

    bf16 *Qs_h, *Qs_l, *WT_h, *WT_l, *Zs_h, *Zs_l, *Qc_h, *Qc_l, *Rc_h, *Rc_l;
    bf16 *HvT_h, *HvT_l, *Ao_h, *Ao_l;
    float *Z, *QRH, *bqrh;
    cudaGetSymbolAddress((void**)&Qs_h, g_Qs_h); cudaGetSymbolAddress((void**)&Qs_l, g_Qs_l);
    cudaGetSymbolAddress((void**)&WT_h, g_WT_h); cudaGetSymbolAddress((void**)&WT_l, g_WT_l);
    cudaGetSymbolAddress((void**)&Z,    g_Z);
    cudaGetSymbolAddress((void**)&Zs_h, g_Zs_h); cudaGetSymbolAddress((void**)&Zs_l, g_Zs_l);
    cudaGetSymbolAddress((void**)&QRH,  g_QRH);
    cudaGetSymbolAddress((void**)&bqrh, g_bqrh);
    cudaGetSymbolAddress((void**)&Qc_h, g_Qc_h); cudaGetSymbolAddress((void**)&Qc_l, g_Qc_l);
    cudaGetSymbolAddress((void**)&Rc_h, g_Rc_h); cudaGetSymbolAddress((void**)&Rc_l, g_Rc_l);
    cudaGetSymbolAddress((void**)&HvT_h, g_HvT_h); cudaGetSymbolAddress((void**)&HvT_l, g_HvT_l);
    cudaGetSymbolAddress((void**)&Ao_h, g_Ao_h); cudaGetSymbolAddress((void**)&Ao_l, g_Ao_l);

    const int SMG = (2 * 128 + 2 * 128) * 72 * 2 * 2;   // 147,456
    cudaFuncSetAttribute(gemm_ps, cudaFuncAttributeMaxDynamicSharedMemorySize, SMG);
    cudaFuncSetAttribute(fused_attn_k, cudaFuncAttributeMaxDynamicSharedMemorySize, FA_SMEM);

    dim3 blk(256), gblk(512);
    long szW = (long)DM * DL;

    // 0) transpose+split weights; split query; combined bias
    transpose_split_k<<<dim3(32, 32, 1), blk>>>(Wz, WT_h + 0 * szW, WT_l + 0 * szW, DL, DM, 1, 0, 0, 0);
    transpose_split_k<<<dim3(32, 32, 1), blk>>>(Wq, WT_h + 1 * szW, WT_l + 1 * szW, DM, DL, 1, 0, 0, 0);
    transpose_split_k<<<dim3(32, 32, 1), blk>>>(Wr, WT_h + 2 * szW, WT_l + 2 * szW, DM, DL, 1, 0, 0, 0);
    transpose_split_k<<<dim3(32, 32, 1), blk>>>(Wh, WT_h + 3 * szW, WT_l + 3 * szW, DM, DL, 1, 0, 0, 0);
    transpose_split_k<<<dim3(32, 32, 1), blk>>>(Wo, WT_h + 4 * szW, WT_l + 4 * szW, DM, DM, 1, 0, 0, 0);
    split_k<<<(TOK * DM / 4 + 255) / 256, blk>>>(query, Qs_h, Qs_l, (long)TOK * DM / 4);
    concat3_k<<<12, blk>>>(bq, br, bh, bqrh);

    // 1) Z = query @ Wz + bz
    gemm_ps<<<dim3(DL / 128, TOK / 128, 1), gblk, SMG>>>(
        Qs_h, Qs_l, WT_h, WT_l, bz, Z, DM, DM, DM, DL);

    // 2) LayerNorm -> split Zs
    layernorm_split_k<<<TOK, blk>>>(Z, Zs_h, Zs_l, ln_g, ln_b);

    // 3) fused Q|R|H projection (N=3072)
    gemm_ps<<<dim3(3 * DM / 128, TOK / 128, 1), gblk, SMG>>>(
        Zs_h, Zs_l, WT_h + szW, WT_l + szW, bqrh, QRH, DL, DL, DL, 3 * DM);

    // 4) phasor -> split Qc, Rc
    phasor_split_k<<<TOK, blk>>>(QRH,          3 * DM, Qc_h, Qc_l, Wphi, bphi);
    phasor_split_k<<<TOK, blk>>>(QRH + DM,     3 * DM, Rc_h, Rc_l, Wphi, bphi);

    // 5) Hv^T per (b,h) with split  (Hv = QRH cols [2048,3072))
    transpose_split_k<<<dim3(HD / 32, Sv / 32, Bv * NH), blk>>>(
        QRH + 2 * DM, HvT_h, HvT_l, 3 * DM, Sv, NH, (long)Sv * 3 * DM, HD, (long)HD * Sv);

    // 6) fused attention -> Ao split
    fused_attn_k<<<dim3(Sv / 64, 1, Bv * NH), blk, FA_SMEM>>>(
        Qc_h, Qc_l, Rc_h, Rc_l, HvT_h, HvT_l, Ao_h, Ao_l);

    // 7) out = Ao @ Wo + bo
    gemm_ps<<<dim3(DM / 128, TOK / 128, 1), gblk, SMG>>>(
        Ao_h, Ao_l, WT_h + 4 * szW, WT_l + 4 * szW, bo, out, DM, DM, DM, DM);
}

// round 6
// speedup vs baseline: 3.0321x; 1.0482x over previous
#include <cuda_runtime.h>
#include <cuda_bf16.h>
#include <math.h>
#include <stdint.h>

typedef __nv_bfloat16 bf16;

#define Bv 2
#define Sv 2048
#define DM 1024
#define NH 16
#define HD 64
#define DL 1024
#define TOK (Bv*Sv)          // 4096
#define LN_EPS 1e-5f
#define NORM_EPS 1e-12f

// ---- scratch (static device globals; allocation-free) ----
__device__ bf16  g_Qs_h[(size_t)TOK * DM],  g_Qs_l[(size_t)TOK * DM];
__device__ bf16  g_WT_h[5 * (size_t)DM * DL], g_WT_l[5 * (size_t)DM * DL];
__device__ float g_Z   [(size_t)TOK * DL];
__device__ bf16  g_Zs_h[(size_t)TOK * DL],  g_Zs_l[(size_t)TOK * DL];
__device__ float g_QRH [(size_t)TOK * 3 * DM];          // Q|R|H fused output
__device__ float g_bqrh[3 * DM];
__device__ bf16  g_Qc_h[(size_t)TOK * NH * 2 * HD], g_Qc_l[(size_t)TOK * NH * 2 * HD];
__device__ bf16  g_Rc_h[(size_t)TOK * NH * 2 * HD], g_Rc_l[(size_t)TOK * NH * 2 * HD];
__device__ bf16  g_HvT_h[(size_t)Bv * NH * HD * Sv], g_HvT_l[(size_t)Bv * NH * HD * Sv];
__device__ bf16  g_Ao_h[(size_t)TOK * DM], g_Ao_l[(size_t)TOK * DM];

// ===========================================================================
// helpers
// ===========================================================================
__device__ __forceinline__ uint32_t smem_u32(const void* p) {
    uint32_t a;
    asm("{ .reg .u64 t; cvta.to.shared.u64 t, %1; cvt.u32.u64 %0, t; }"
        : "=r"(a) : "l"(p));
    return a;
}
__device__ __forceinline__ void mma_bf16(float* d, const uint32_t* a, const uint32_t* b) {
    asm volatile(
        "mma.sync.aligned.m16n8k16.row.col.f32.bf16.bf16.f32 "
        "{%0,%1,%2,%3}, {%4,%5,%6,%7}, {%8,%9}, {%0,%1,%2,%3};"
        : "+f"(d[0]), "+f"(d[1]), "+f"(d[2]), "+f"(d[3])
        : "r"(a[0]), "r"(a[1]), "r"(a[2]), "r"(a[3]), "r"(b[0]), "r"(b[1]));
}
__device__ __forceinline__ void ldmx4(uint32_t* r, uint32_t addr) {
    asm volatile("ldmatrix.sync.aligned.m8n8.x4.shared.b16 {%0,%1,%2,%3}, [%4];"
                 : "=r"(r[0]), "=r"(r[1]), "=r"(r[2]), "=r"(r[3]) : "r"(addr));
}
__device__ __forceinline__ void cpa16(uint32_t dst, const void* src) {
    asm volatile("cp.async.cg.shared.global [%0], [%1], 16;" :: "r"(dst), "l"(src));
}
__device__ __forceinline__ void cp_commit() { asm volatile("cp.async.commit_group;"); }
template<int N> __device__ __forceinline__ void cp_wait() {
    asm volatile("cp.async.wait_group %0;" :: "n"(N));
}
__device__ __forceinline__ uint32_t packhi2(float a, float b) {
    __nv_bfloat162 t = __floats2bfloat162_rn(a, b);
    return *reinterpret_cast<uint32_t*>(&t);
}
__device__ __forceinline__ void split4(float4 v, uint2& hh, uint2& ll) {
    bf16 hx = __float2bfloat16(v.x), hy = __float2bfloat16(v.y);
    bf16 hz = __float2bfloat16(v.z), hw = __float2bfloat16(v.w);
    float lx = v.x - __bfloat162float(hx), ly = v.y - __bfloat162float(hy);
    float lz = v.z - __bfloat162float(hz), lw = v.w - __bfloat162float(hw);
    __nv_bfloat162 h0 = {hx, hy}, h1 = {hz, hw};
    hh.x = *reinterpret_cast<uint32_t*>(&h0); hh.y = *reinterpret_cast<uint32_t*>(&h1);
    ll.x = packhi2(lx, ly); ll.y = packhi2(lz, lw);
}
__device__ __forceinline__ void split2(float a, float b, uint32_t& hp, uint32_t& lp) {
    bf16 ha = __float2bfloat16(a), hb = __float2bfloat16(b);
    hp = packhi2(__bfloat162float(ha), __bfloat162float(hb));
    lp = packhi2(a - __bfloat162float(ha), b - __bfloat162float(hb));
}

// ===========================================================================
// Batched NT GEMM on presplit bf16 hi/lo operands (3-term compensated)
// BM=128, BN=128, BK=64, 512 threads, double-buffered cp.async, ldmatrix frags
// ===========================================================================
__global__ void __launch_bounds__(512, 1)
gemm_ps(const bf16* __restrict__ Ah_, const bf16* __restrict__ Al_,
        const bf16* __restrict__ Bh_, const bf16* __restrict__ Bl_,
        const float* __restrict__ bias, float* __restrict__ Cf,
        int K, long lda, long ldb, long ldc)
{
    constexpr int BM = 128, BN = 128, BK = 64;
    constexpr int PA = 72;
    constexpr int SBUF = (2 * BM + 2 * BN) * PA;
    constexpr int OAh = 0, OAl = BM * PA, OBh = 2 * BM * PA, OBl = 2 * BM * PA + BN * PA;
    constexpr int AIT = 4, BIT = 4;
    constexpr int SP = BN + 4;

    extern __shared__ char smem_raw[];
    bf16* sm = (bf16*)smem_raw;
    float* stg = (float*)smem_raw;
    uint32_t smbase = smem_u32(smem_raw);

    int tid = threadIdx.x, wid = tid >> 5, lane = tid & 31;
    int gid = lane >> 2, tig = lane & 3;
    int seg = lane >> 3, sl = lane & 7;
    int wm0 = (wid >> 2) * 32, wn0 = (wid & 3) * 32;

    int row0 = blockIdx.y * BM, col0 = blockIdx.x * BN;
    const bf16* AhP = Ah_ + (long)row0 * lda;
    const bf16* AlP = Al_ + (long)row0 * lda;
    const bf16* BhP = Bh_ + (long)col0 * ldb;
    const bf16* BlP = Bl_ + (long)col0 * ldb;

    const bf16* asrc[AIT]; uint32_t adst[AIT];
#pragma unroll
    for (int i = 0; i < AIT; i++) {
        int idx = tid + i * 512;
        int lo = idx >= BM * 8;
        int w = idx - lo * BM * 8;
        int r = w >> 3, kc = w & 7;
        asrc[i] = (lo ? AlP : AhP) + (long)r * lda + kc * 8;
        adst[i] = smbase + 2u * ((lo ? OAl : OAh) + r * PA + kc * 8);
    }
    const bf16* bsrc[BIT]; uint32_t bdst[BIT];
#pragma unroll
    for (int i = 0; i < BIT; i++) {
        int idx = tid + i * 512;
        int lo = idx >= BN * 8;
        int w = idx - lo * BN * 8;
        int r = w >> 3, kc = w & 7;
        bsrc[i] = (lo ? BlP : BhP) + (long)r * ldb + kc * 8;
        bdst[i] = smbase + 2u * ((lo ? OBl : OBh) + r * PA + kc * 8);
    }

    // ldmatrix fragment addresses
    uint32_t aadr_h[2], aadr_l[2], badr_h[2], badr_l[2];
#pragma unroll
    for (int mi = 0; mi < 2; mi++) {
        int rowA = wm0 + mi * 16 + (seg & 1) * 8 + sl;
        int colA = (seg >> 1) * 8;
        aadr_h[mi] = smbase + 2u * (OAh + rowA * PA + colA);
        aadr_l[mi] = smbase + 2u * (OAl + rowA * PA + colA);
    }
#pragma unroll
    for (int nj = 0; nj < 2; nj++) {
        int rowB = wn0 + nj * 16 + (seg >> 1) * 8 + sl;
        int colB = (seg & 1) * 8;
        badr_h[nj] = smbase + 2u * (OBh + rowB * PA + colB);
        badr_l[nj] = smbase + 2u * (OBl + rowB * PA + colB);
    }

    float acc[2][4][4];
#pragma unroll
    for (int mi = 0; mi < 2; mi++)
#pragma unroll
        for (int ni = 0; ni < 4; ni++)
#pragma unroll
            for (int j = 0; j < 4; j++) acc[mi][ni][j] = 0.f;

    const int NS = K / BK;
    {
#pragma unroll
        for (int i = 0; i < AIT; i++) cpa16(adst[i], asrc[i]);
#pragma unroll
        for (int i = 0; i < BIT; i++) cpa16(bdst[i], bsrc[i]);
        cp_commit();
    }
    for (int s = 0; s < NS; s++) {
        if (s + 1 < NS) {
            long ko = (long)(s + 1) * BK;
            uint32_t boff = ((s + 1) & 1) * (uint32_t)(SBUF * 2);
#pragma unroll
            for (int i = 0; i < AIT; i++) cpa16(adst[i] + boff, asrc[i] + ko);
#pragma unroll
            for (int i = 0; i < BIT; i++) cpa16(bdst[i] + boff, bsrc[i] + ko);
            cp_commit();
            cp_wait<1>();
        } else {
            cp_wait<0>();
        }
        __syncthreads();
        uint32_t soff = (s & 1) * (uint32_t)(SBUF * 2);
#pragma unroll
        for (int kk = 0; kk < 4; kk++) {
            uint32_t off = soff + 32u * kk;
            uint32_t ah[2][4], al[2][4], bh[2][4], bl[2][4];
#pragma unroll
            for (int mi = 0; mi < 2; mi++) {
                ldmx4(ah[mi], aadr_h[mi] + off);
                ldmx4(al[mi], aadr_l[mi] + off);
            }
#pragma unroll
            for (int nj = 0; nj < 2; nj++) {
                ldmx4(bh[nj], badr_h[nj] + off);
                ldmx4(bl[nj], badr_l[nj] + off);
            }
#pragma unroll
            for (int mi = 0; mi < 2; mi++)
#pragma unroll
                for (int ni = 0; ni < 4; ni++) {
                    int nj = ni >> 1, hf = (ni & 1) * 2;
                    mma_bf16(acc[mi][ni], ah[mi], &bh[nj][hf]);
                    mma_bf16(acc[mi][ni], ah[mi], &bl[nj][hf]);
                    mma_bf16(acc[mi][ni], al[mi], &bh[nj][hf]);
                }
        }
        __syncthreads();
    }

#pragma unroll
    for (int mi = 0; mi < 2; mi++)
#pragma unroll
        for (int ni = 0; ni < 4; ni++) {
            int r = wm0 + mi * 16 + gid;
            int c = wn0 + ni * 8 + tig * 2;
            stg[r * SP + c]           = acc[mi][ni][0];
            stg[r * SP + c + 1]       = acc[mi][ni][1];
            stg[(r + 8) * SP + c]     = acc[mi][ni][2];
            stg[(r + 8) * SP + c + 1] = acc[mi][ni][3];
        }
    __syncthreads();
#pragma unroll
    for (int i = 0; i < 8; i++) {
        int idx = tid + i * 512;
        int row = idx >> 5, c4 = (idx & 31) * 4;
        float4 v = *(const float4*)(stg + row * SP + c4);
        int col = col0 + c4;
        if (bias) {
            float4 bv = *(const float4*)&bias[col];
            v.x += bv.x; v.y += bv.y; v.z += bv.z; v.w += bv.w;
        }
        *(float4*)&Cf[(long)(row0 + row) * ldc + col] = v;
    }
}

// ===========================================================================
// Fused attention: per (b,h,q-tile 128): S = Qc@Rc^T (regs), sumsq, U += S@Hv,
// then U / max(||row||,eps) -> Ao split. 512 threads, 16 warps (4m x 4n).
// ===========================================================================
#define NT 32            // r-tiles of 64
#define QT 128
#define PQ 136           // Qc/Rc smem pitch (bf16), K=128
#define PH 72            // Hv smem pitch, K-slice=64
#define STG_E (2*64*PQ + 2*64*PH)    // 26624 bf16 per stage
#define ORH 0
#define ORL (64*PQ)
#define OHH (2*64*PQ)
#define OHL (2*64*PQ + 64*PH)
#define OQH (2*STG_E)
#define OQL (2*STG_E + QT*PQ)
#define FA_SMEM ((2*STG_E + 2*QT*PQ) * 2)   // 176,128 bytes

__global__ void __launch_bounds__(512, 1)
fused_attn_k(const bf16* __restrict__ Qch, const bf16* __restrict__ Qcl,
             const bf16* __restrict__ Rch, const bf16* __restrict__ Rcl,
             const bf16* __restrict__ Hth, const bf16* __restrict__ Htl,
             bf16* __restrict__ Aoh, bf16* __restrict__ Aol)
{
    extern __shared__ char smem_raw[];
    uint32_t smbase = smem_u32(smem_raw);

    int tid = threadIdx.x, wid = tid >> 5, lane = tid & 31;
    int gid = lane >> 2, tig = lane & 3;
    int seg = lane >> 3, sl = lane & 7;
    int mw = wid >> 2, nw = wid & 3;     // 4 m-warps x 4 n-warps

    int qt = blockIdx.x, z = blockIdx.z;
    int b = z >> 4, h = z & 15;
    int row0 = qt * QT;
    long qtok = ((long)(b * Sv + row0)) * 2048 + h * 128;
    long zHv = (long)z * HD * Sv;

    // ---- Qc prologue loads (8 chunks/thread, 128 rows) ----
#pragma unroll
    for (int i = 0; i < 8; i++) {
        int idx = tid + i * 512;
        int comp = idx >> 11;
        int w = idx & 2047;
        int r = w >> 4, kc = w & 15;
        const bf16* src = (comp ? Qcl : Qch) + qtok + (long)r * 2048 + kc * 8;
        cpa16(smbase + 2u * ((comp ? OQL : OQH) + r * PQ + kc * 8), src);
    }
    // ---- stage 0 loads ----
    {
        long rtok = ((long)(b * Sv)) * 2048 + h * 128;
#pragma unroll
        for (int i = 0; i < 4; i++) {
            int idx = tid + i * 512;
            int comp = idx >> 10;
            int w = idx & 1023;
            int r = w >> 4, kc = w & 15;
            const bf16* src = (comp ? Rcl : Rch) + rtok + (long)r * 2048 + kc * 8;
            cpa16(smbase + 2u * ((comp ? ORL : ORH) + r * PQ + kc * 8), src);
        }
#pragma unroll
        for (int i = 0; i < 2; i++) {
            int idx = tid + i * 512;
            int comp = idx >> 9;
            int w = idx & 511;
            int n = w >> 3, kc = w & 7;
            const bf16* src = (comp ? Htl : Hth) + zHv + (long)n * 2048 + kc * 8;
            cpa16(smbase + 2u * ((comp ? OHL : OHH) + n * PH + kc * 8), src);
        }
        cp_commit();
    }

    // ldmatrix fragment addresses
    uint32_t qadr_h[2], qadr_l[2];
#pragma unroll
    for (int mi = 0; mi < 2; mi++) {
        int rowA = mw * 32 + mi * 16 + (seg & 1) * 8 + sl;
        int colA = (seg >> 1) * 8;
        qadr_h[mi] = smbase + 2u * (OQH + rowA * PQ + colA);
        qadr_l[mi] = smbase + 2u * (OQL + rowA * PQ + colA);
    }
    uint32_t radr_h, radr_l;
    {
        int rowB = nw * 16 + (seg >> 1) * 8 + sl;
        int colB = (seg & 1) * 8;
        radr_h = smbase + 2u * (ORH + rowB * PQ + colB);
        radr_l = smbase + 2u * (ORL + rowB * PQ + colB);
    }
    uint32_t hadr_h[4], hadr_l[4];
#pragma unroll
    for (int nj = 0; nj < 4; nj++) {
        int rowH = nj * 16 + (seg >> 1) * 8 + sl;
        int colH = (seg & 1) * 8 + nw * 16;     // warp k-slice baked in
        hadr_h[nj] = smbase + 2u * (OHH + rowH * PH + colH);
        hadr_l[nj] = smbase + 2u * (OHL + rowH * PH + colH);
    }

    float U[2][8][4];
#pragma unroll
    for (int mi = 0; mi < 2; mi++)
#pragma unroll
        for (int ni = 0; ni < 8; ni++)
#pragma unroll
            for (int j = 0; j < 4; j++) U[mi][ni][j] = 0.f;
    float sqacc[2][2] = {{0.f, 0.f}, {0.f, 0.f}};

    for (int t = 0; t < NT; t++) {
        if (t + 1 < NT) {
            uint32_t boff = ((t + 1) & 1) * (uint32_t)(STG_E * 2);
            long rtok = ((long)(b * Sv + (t + 1) * 64)) * 2048 + h * 128;
            long hoff = zHv + (t + 1) * 64;
#pragma unroll
            for (int i = 0; i < 4; i++) {
                int idx = tid + i * 512;
                int comp = idx >> 10;
                int w = idx & 1023;
                int r = w >> 4, kc = w & 15;
                const bf16* src = (comp ? Rcl : Rch) + rtok + (long)r * 2048 + kc * 8;
                cpa16(smbase + boff + 2u * ((comp ? ORL : ORH) + r * PQ + kc * 8), src);
            }
#pragma unroll
            for (int i = 0; i < 2; i++) {
                int idx = tid + i * 512;
                int comp = idx >> 9;
                int w = idx & 511;
                int n = w >> 3, kc = w & 7;
                const bf16* src = (comp ? Htl : Hth) + hoff + (long)n * 2048 + kc * 8;
                cpa16(smbase + boff + 2u * ((comp ? OHL : OHH) + n * PH + kc * 8), src);
            }
            cp_commit();
            cp_wait<1>();
        } else {
            cp_wait<0>();
        }
        __syncthreads();
        uint32_t soff = (t & 1) * (uint32_t)(STG_E * 2);

        // ---- Phase A: S tile (128 q x 64 r); warp rows mw*32..+32, cols nw*16..+16
        float sacc[2][2][4];
#pragma unroll
        for (int mi = 0; mi < 2; mi++)
#pragma unroll
            for (int ni = 0; ni < 2; ni++)
#pragma unroll
                for (int j = 0; j < 4; j++) sacc[mi][ni][j] = 0.f;
#pragma unroll
        for (int kk = 0; kk < 8; kk++) {
            uint32_t koff = 32u * kk;
            uint32_t ah[2][4], al[2][4], bh[4], bl[4];
#pragma unroll
            for (int mi = 0; mi < 2; mi++) {
                ldmx4(ah[mi], qadr_h[mi] + koff);
                ldmx4(al[mi], qadr_l[mi] + koff);
            }
            ldmx4(bh, radr_h + soff + koff);
            ldmx4(bl, radr_l + soff + koff);
#pragma unroll
            for (int mi = 0; mi < 2; mi++)
#pragma unroll
                for (int ni = 0; ni < 2; ni++) {
                    mma_bf16(sacc[mi][ni], ah[mi], &bh[ni * 2]);
                    mma_bf16(sacc[mi][ni], ah[mi], &bl[ni * 2]);
                    mma_bf16(sacc[mi][ni], al[mi], &bh[ni * 2]);
                }
        }
        // ---- sumsq accumulate ----
#pragma unroll
        for (int mi = 0; mi < 2; mi++) {
            float s0 = 0.f, s1 = 0.f;
#pragma unroll
            for (int ni = 0; ni < 2; ni++) {
                s0 += sacc[mi][ni][0] * sacc[mi][ni][0] + sacc[mi][ni][1] * sacc[mi][ni][1];
                s1 += sacc[mi][ni][2] * sacc[mi][ni][2] + sacc[mi][ni][3] * sacc[mi][ni][3];
            }
            sqacc[mi][0] += s0; sqacc[mi][1] += s1;
        }
        // ---- Phase B: U += S(split) @ Hv-slice (warp k-slice = its 16 S-cols)
        uint32_t a2h[2][4], a2l[2][4];
#pragma unroll
        for (int mi = 0; mi < 2; mi++) {
            split2(sacc[mi][0][0], sacc[mi][0][1], a2h[mi][0], a2l[mi][0]);
            split2(sacc[mi][0][2], sacc[mi][0][3], a2h[mi][1], a2l[mi][1]);
            split2(sacc[mi][1][0], sacc[mi][1][1], a2h[mi][2], a2l[mi][2]);
            split2(sacc[mi][1][2], sacc[mi][1][3], a2h[mi][3], a2l[mi][3]);
        }
#pragma unroll
        for (int nj = 0; nj < 4; nj++) {
            uint32_t bh2[4], bl2[4];
            ldmx4(bh2, hadr_h[nj] + soff);
            ldmx4(bl2, hadr_l[nj] + soff);
#pragma unroll
            for (int hf = 0; hf < 2; hf++) {
                int ni = nj * 2 + hf;
#pragma unroll
                for (int mi = 0; mi < 2; mi++) {
                    mma_bf16(U[mi][ni], a2h[mi], &bh2[hf * 2]);
                    mma_bf16(U[mi][ni], a2h[mi], &bl2[hf * 2]);
                    mma_bf16(U[mi][ni], a2l[mi], &bh2[hf * 2]);
                }
            }
        }
        __syncthreads();
    }

    // ================= epilogue =================
    float* Ured = (float*)smem_raw;             // 128 x 68 fp32 (reuse stages)
    float* sq = (float*)(smem_raw + QT * 68 * 4);
    if (tid < QT) sq[tid] = 0.f;
    __syncthreads();
#pragma unroll
    for (int mi = 0; mi < 2; mi++)
#pragma unroll
        for (int hh = 0; hh < 2; hh++) {
            float v = sqacc[mi][hh];
            v += __shfl_xor_sync(0xFFFFFFFF, v, 1);
            v += __shfl_xor_sync(0xFFFFFFFF, v, 2);
            if (tig == 0) atomicAdd(&sq[mw * 32 + mi * 16 + gid + hh * 8], v);
        }
    __syncthreads();
    if (tid < QT) sq[tid] = 1.0f / fmaxf(sqrtf(sq[tid]), NORM_EPS);
    // U cross-warp reduction (staged, deterministic over nw)
    for (int w = 0; w < 4; w++) {
        if (nw == w) {
#pragma unroll
            for (int mi = 0; mi < 2; mi++)
#pragma unroll
                for (int ni = 0; ni < 8; ni++) {
                    int r = mw * 32 + mi * 16 + gid;
                    int c = ni * 8 + tig * 2;
                    if (w == 0) {
                        Ured[r * 68 + c]           = U[mi][ni][0];
                        Ured[r * 68 + c + 1]       = U[mi][ni][1];
                        Ured[(r + 8) * 68 + c]     = U[mi][ni][2];
                        Ured[(r + 8) * 68 + c + 1] = U[mi][ni][3];
                    } else {
                        Ured[r * 68 + c]           += U[mi][ni][0];
                        Ured[r * 68 + c + 1]       += U[mi][ni][1];
                        Ured[(r + 8) * 68 + c]     += U[mi][ni][2];
                        Ured[(r + 8) * 68 + c + 1] += U[mi][ni][3];
                    }
                }
        }
        __syncthreads();
    }
#pragma unroll
    for (int i = 0; i < 4; i++) {
        int idx = tid + i * 512;
        int r = idx >> 4, c4 = (idx & 15) * 4;
        float sc = sq[r];
        float4 v = *(const float4*)(Ured + r * 68 + c4);
        v.x *= sc; v.y *= sc; v.z *= sc; v.w *= sc;
        uint2 hh, ll;
        split4(v, hh, ll);
        long gpos = ((long)(b * Sv + row0 + r)) * DM + h * 64 + c4;
        *(uint2*)&Aoh[gpos] = hh;
        *(uint2*)&Aol[gpos] = ll;
    }
}

// ===========================================================================
// small kernels
// ===========================================================================
__global__ void split_k(const float* __restrict__ x, bf16* __restrict__ h,
                        bf16* __restrict__ l, long n4)
{
    long i = (long)blockIdx.x * 256 + threadIdx.x;
    if (i >= n4) return;
    float4 v = *(const float4*)&x[i * 4];
    uint2 hh, ll;
    split4(v, hh, ll);
    *(uint2*)&h[i * 4] = hh;
    *(uint2*)&l[i * 4] = ll;
}

__global__ void transpose_split_k(const float* __restrict__ in,
                                  bf16* __restrict__ oh, bf16* __restrict__ ol,
                                  long ldi, long ldo, int H,
                                  long sIb, long sIh, long sOz)
{
    __shared__ float t[32][33];
    int z = blockIdx.z, b = z / H, h = z - b * H;
    in += (long)b * sIb + (long)h * sIh;
    oh += (long)z * sOz; ol += (long)z * sOz;
    int x0 = blockIdx.x * 32, y0 = blockIdx.y * 32;
    int tx = threadIdx.x & 31, ty = threadIdx.x >> 5;
#pragma unroll
    for (int i = 0; i < 4; i++)
        t[ty + i * 8][tx] = in[(long)(y0 + ty + i * 8) * ldi + x0 + tx];
    __syncthreads();
#pragma unroll
    for (int i = 0; i < 4; i++) {
        float v = t[tx][ty + i * 8];
        bf16 hv = __float2bfloat16(v);
        long o = (long)(x0 + ty + i * 8) * ldo + y0 + tx;
        oh[o] = hv;
        ol[o] = __float2bfloat16(v - __bfloat162float(hv));
    }
}

__global__ void layernorm_split_k(const float* __restrict__ Z,
                                  bf16* __restrict__ oh, bf16* __restrict__ ol,
                                  const float* __restrict__ g, const float* __restrict__ be)
{
    __shared__ float red[256];
    int tid = threadIdx.x;
    const float* row = Z + (long)blockIdx.x * DL;
    float v[4];
#pragma unroll
    for (int t = 0; t < 4; t++) v[t] = row[tid + t * 256];
    float s = v[0] + v[1] + v[2] + v[3];
    red[tid] = s; __syncthreads();
    for (int off = 128; off > 0; off >>= 1) {
        if (tid < off) red[tid] += red[tid + off];
        __syncthreads();
    }
    float mu = red[0] * (1.0f / DL);
    __syncthreads();
    float vs = 0.f;
#pragma unroll
    for (int t = 0; t < 4; t++) { float d = v[t] - mu; vs += d * d; }
    red[tid] = vs; __syncthreads();
    for (int off = 128; off > 0; off >>= 1) {
        if (tid < off) red[tid] += red[tid + off];
        __syncthreads();
    }
    float rstd = rsqrtf(red[0] * (1.0f / DL) + LN_EPS);
    long base = (long)blockIdx.x * DL;
#pragma unroll
    for (int t = 0; t < 4; t++) {
        int i = tid + t * 256;
        float o = (v[t] - mu) * rstd * g[i] + be[i];
        bf16 hv = __float2bfloat16(o);
        oh[base + i] = hv;
        ol[base + i] = __float2bfloat16(o - __bfloat162float(hv));
    }
}

__global__ void phasor_split_k(const float* __restrict__ Qin, long ldq,
                               bf16* __restrict__ oh, bf16* __restrict__ ol,
                               const float* __restrict__ Wphi, const float* __restrict__ bphi)
{
    __shared__ float W[HD][HD];
    __shared__ float qrow[4][HD + 4];
    int tid = threadIdx.x;
    int j = tid & 63, g = tid >> 6;
    for (int i = tid; i < HD * HD; i += 256) W[i >> 6][i & 63] = Wphi[i];
    __syncthreads();
    const float* base = Qin + (long)blockIdx.x * ldq;
    long obase = (long)blockIdx.x * (NH * 2 * HD);
    float bj = bphi[j];
    for (int hb = 0; hb < NH; hb += 4) {
        int h = hb + g;
        qrow[g][j] = base[h * HD + j];
        __syncthreads();
        float phi = bj;
#pragma unroll 16
        for (int d = 0; d < HD; d++) phi += qrow[g][d] * W[d][j];
        float q = qrow[g][j];
        float sp, cp;
        sincosf(phi, &sp, &cp);
        float vc = q * cp, vsn = q * sp;
        bf16 hc = __float2bfloat16(vc), hs = __float2bfloat16(vsn);
        long oc = obase + h * 2 * HD + j;
        oh[oc] = hc;      ol[oc] = __float2bfloat16(vc - __bfloat162float(hc));
        oh[oc + HD] = hs; ol[oc + HD] = __float2bfloat16(vsn - __bfloat162float(hs));
        __syncthreads();
    }
}

__global__ void concat3_k(const float* __restrict__ a, const float* __restrict__ b,
                          const float* __restrict__ c, float* __restrict__ o)
{
    int i = blockIdx.x * 256 + threadIdx.x;
    if (i < DM) o[i] = a[i];
    else if (i < 2 * DM) o[i] = b[i - DM];
    else if (i < 3 * DM) o[i] = c[i - 2 * DM];
}

// ===========================================================================
extern "C" void kernel_launch(void* const* d_in, const int* in_sizes, int n_in,
                              void* d_out, int out_size)
{
    const float* query = (const float*)d_in[0];
    const float* Wz   = (const float*)d_in[3];
    const float* bz   = (const float*)d_in[4];
    const float* ln_g = (const float*)d_in[5];
    const float* ln_b = (const float*)d_in[6];
    const float* Wq   = (const float*)d_in[7];
    const float* bq   = (const float*)d_in[8];
    const float* Wr   = (const float*)d_in[9];
    const float* br   = (const float*)d_in[10];
    const float* Wh   = (const float*)d_in[11];
    const float* bh   = (const float*)d_in[12];
    const float* Wphi = (const float*)d_in[13];
    const float* bphi = (const float*)d_in[14];
    const float* Wo   = (const float*)d_in[15];
    const float* bo   = (const float*)d_in[16];
    float* out = (float*)d_out;

    bf16 *Qs_h, *Qs_l, *WT_h, *WT_l, *Zs_h, *Zs_l, *Qc_h, *Qc_l, *Rc_h, *Rc_l;
    bf16 *HvT_h, *HvT_l, *Ao_h, *Ao_l;
    float *Z, *QRH, *bqrh;
    cudaGetSymbolAddress((void**)&Qs_h, g_Qs_h); cudaGetSymbolAddress((void**)&Qs_l, g_Qs_l);
    cudaGetSymbolAddress((void**)&WT_h, g_WT_h); cudaGetSymbolAddress((void**)&WT_l, g_WT_l);
    cudaGetSymbolAddress((void**)&Z,    g_Z);
    cudaGetSymbolAddress((void**)&Zs_h, g_Zs_h); cudaGetSymbolAddress((void**)&Zs_l, g_Zs_l);
    cudaGetSymbolAddress((void**)&QRH,  g_QRH);
    cudaGetSymbolAddress((void**)&bqrh, g_bqrh);
    cudaGetSymbolAddress((void**)&Qc_h, g_Qc_h); cudaGetSymbolAddress((void**)&Qc_l, g_Qc_l);
    cudaGetSymbolAddress((void**)&Rc_h, g_Rc_h); cudaGetSymbolAddress((void**)&Rc_l, g_Rc_l);
    cudaGetSymbolAddress((void**)&HvT_h, g_HvT_h); cudaGetSymbolAddress((void**)&HvT_l, g_HvT_l);
    cudaGetSymbolAddress((void**)&Ao_h, g_Ao_h); cudaGetSymbolAddress((void**)&Ao_l, g_Ao_l);

    const int SMG = (2 * 128 + 2 * 128) * 72 * 2 * 2;   // 147,456
    cudaFuncSetAttribute(gemm_ps, cudaFuncAttributeMaxDynamicSharedMemorySize, SMG);
    cudaFuncSetAttribute(fused_attn_k, cudaFuncAttributeMaxDynamicSharedMemorySize, FA_SMEM);

    dim3 blk(256), gblk(512);
    long szW = (long)DM * DL;

    // 0) transpose+split weights; split query; combined bias
    transpose_split_k<<<dim3(32, 32, 1), blk>>>(Wz, WT_h + 0 * szW, WT_l + 0 * szW, DL, DM, 1, 0, 0, 0);
    transpose_split_k<<<dim3(32, 32, 1), blk>>>(Wq, WT_h + 1 * szW, WT_l + 1 * szW, DM, DL, 1, 0, 0, 0);
    transpose_split_k<<<dim3(32, 32, 1), blk>>>(Wr, WT_h + 2 * szW, WT_l + 2 * szW, DM, DL, 1, 0, 0, 0);
    transpose_split_k<<<dim3(32, 32, 1), blk>>>(Wh, WT_h + 3 * szW, WT_l + 3 * szW, DM, DL, 1, 0, 0, 0);
    transpose_split_k<<<dim3(32, 32, 1), blk>>>(Wo, WT_h + 4 * szW, WT_l + 4 * szW, DM, DM, 1, 0, 0, 0);
    split_k<<<(TOK * DM / 4 + 255) / 256, blk>>>(query, Qs_h, Qs_l, (long)TOK * DM / 4);
    concat3_k<<<12, blk>>>(bq, br, bh, bqrh);

    // 1) Z = query @ Wz + bz
    gemm_ps<<<dim3(DL / 128, TOK / 128, 1), gblk, SMG>>>(
        Qs_h, Qs_l, WT_h, WT_l, bz, Z, DM, DM, DM, DL);

    // 2) LayerNorm -> split Zs
    layernorm_split_k<<<TOK, blk>>>(Z, Zs_h, Zs_l, ln_g, ln_b);

    // 3) fused Q|R|H projection (N=3072)
    gemm_ps<<<dim3(3 * DM / 128, TOK / 128, 1), gblk, SMG>>>(
        Zs_h, Zs_l, WT_h + szW, WT_l + szW, bqrh, QRH, DL, DL, DL, 3 * DM);

    // 4) phasor -> split Qc, Rc
    phasor_split_k<<<TOK, blk>>>(QRH,      3 * DM, Qc_h, Qc_l, Wphi, bphi);
    phasor_split_k<<<TOK, blk>>>(QRH + DM, 3 * DM, Rc_h, Rc_l, Wphi, bphi);

    // 5) Hv^T per (b,h) with split (Hv = QRH cols [2048,3072))
    transpose_split_k<<<dim3(HD / 32, Sv / 32, Bv * NH), blk>>>(
        QRH + 2 * DM, HvT_h, HvT_l, 3 * DM, Sv, NH, (long)Sv * 3 * DM, HD, (long)HD * Sv);

    // 6) fused attention -> Ao split
    fused_attn_k<<<dim3(Sv / QT, 1, Bv * NH), gblk, FA_SMEM>>>(
        Qc_h, Qc_l, Rc_h, Rc_l, HvT_h, HvT_l, Ao_h, Ao_l);

    // 7) out = Ao @ Wo + bo
    gemm_ps<<<dim3(DM / 128, TOK / 128, 1), gblk, SMG>>>(
        Ao_h, Ao_l, WT_h + 4 * szW, WT_l + 4 * szW, bo, out, DM, DM, DM, DM);
}

// round 8
// speedup vs baseline: 4.0079x; 1.3218x over previous
#include <cuda_runtime.h>
#include <cuda_fp16.h>
#include <math.h>
#include <stdint.h>

typedef __half h16;

#define Bv 2
#define Sv 2048
#define DM 1024
#define NH 16
#define HD 64
#define DL 1024
#define TOK (Bv*Sv)          // 4096
#define LN_EPS 1e-5f
#define NORM_EPS 1e-12f

// ---- scratch (static device globals; allocation-free) ----
__device__ h16   g_Qs_h[(size_t)TOK * DM],  g_Qs_l[(size_t)TOK * DM];
__device__ h16   g_WT_h[5 * (size_t)DM * DL];                 // weights: hi only
__device__ float g_Z   [(size_t)TOK * DL];
__device__ h16   g_Zs_h[(size_t)TOK * DL],  g_Zs_l[(size_t)TOK * DL];
__device__ float g_QRH [(size_t)TOK * 3 * DM];
__device__ float g_bqrh[3 * DM];
__device__ h16   g_Qc_h[(size_t)TOK * NH * 2 * HD], g_Qc_l[(size_t)TOK * NH * 2 * HD];
__device__ h16   g_Rc_h[(size_t)TOK * NH * 2 * HD];           // hi only (B side)
__device__ h16   g_HvT_h[(size_t)Bv * NH * HD * Sv];          // hi only (B side)
__device__ h16   g_Ao_h[(size_t)TOK * DM], g_Ao_l[(size_t)TOK * DM];

// ===========================================================================
// helpers
// ===========================================================================
__device__ __forceinline__ uint32_t smem_u32(const void* p) {
    uint32_t a;
    asm("{ .reg .u64 t; cvta.to.shared.u64 t, %1; cvt.u32.u64 %0, t; }"
        : "=r"(a) : "l"(p));
    return a;
}
__device__ __forceinline__ void mma_f16(float* d, const uint32_t* a, const uint32_t* b) {
    asm volatile(
        "mma.sync.aligned.m16n8k16.row.col.f32.f16.f16.f32 "
        "{%0,%1,%2,%3}, {%4,%5,%6,%7}, {%8,%9}, {%0,%1,%2,%3};"
        : "+f"(d[0]), "+f"(d[1]), "+f"(d[2]), "+f"(d[3])
        : "r"(a[0]), "r"(a[1]), "r"(a[2]), "r"(a[3]), "r"(b[0]), "r"(b[1]));
}
__device__ __forceinline__ void ldmx4(uint32_t* r, uint32_t addr) {
    asm volatile("ldmatrix.sync.aligned.m8n8.x4.shared.b16 {%0,%1,%2,%3}, [%4];"
                 : "=r"(r[0]), "=r"(r[1]), "=r"(r[2]), "=r"(r[3]) : "r"(addr));
}
__device__ __forceinline__ void cpa16(uint32_t dst, const void* src) {
    asm volatile("cp.async.cg.shared.global [%0], [%1], 16;" :: "r"(dst), "l"(src));
}
__device__ __forceinline__ void cp_commit() { asm volatile("cp.async.commit_group;"); }
template<int N> __device__ __forceinline__ void cp_wait() {
    asm volatile("cp.async.wait_group %0;" :: "n"(N));
}
__device__ __forceinline__ uint32_t packh2(float a, float b) {
    __half2 t = __floats2half2_rn(a, b);
    return *reinterpret_cast<uint32_t*>(&t);
}
__device__ __forceinline__ void split4h(float4 v, uint2& hh, uint2& ll) {
    h16 ax = __float2half(v.x), ay = __float2half(v.y);
    h16 az = __float2half(v.z), aw = __float2half(v.w);
    __half2 h0 = {ax, ay}, h1 = {az, aw};
    hh.x = *reinterpret_cast<uint32_t*>(&h0); hh.y = *reinterpret_cast<uint32_t*>(&h1);
    ll.x = packh2(v.x - __half2float(ax), v.y - __half2float(ay));
    ll.y = packh2(v.z - __half2float(az), v.w - __half2float(aw));
}
__device__ __forceinline__ void round4h(float4 v, uint2& hh) {
    hh.x = packh2(v.x, v.y); hh.y = packh2(v.z, v.w);
}
__device__ __forceinline__ void split2h(float a, float b, uint32_t& hp, uint32_t& lp) {
    h16 ha = __float2half(a), hb = __float2half(b);
    __half2 t = {ha, hb};
    hp = *reinterpret_cast<uint32_t*>(&t);
    lp = packh2(a - __half2float(ha), b - __half2float(hb));
}

// ===========================================================================
// NT GEMM: C = (Ah+Al) @ Bh^T (+bias). A fp16 split, B fp16 rounded. 2 MMAs.
// BM=128, BN=128, BK=64, 512 threads, double-buffered cp.async, ldmatrix
// ===========================================================================
__global__ void __launch_bounds__(512, 1)
gemm_ps(const h16* __restrict__ Ah_, const h16* __restrict__ Al_,
        const h16* __restrict__ Bh_,
        const float* __restrict__ bias, float* __restrict__ Cf,
        int K, long lda, long ldb, long ldc)
{
    constexpr int BM = 128, BN = 128, BK = 64;
    constexpr int PA = 72;
    constexpr int SBUF = (2 * BM + BN) * PA;          // 27648 elems
    constexpr int OAh = 0, OAl = BM * PA, OBh = 2 * BM * PA;
    constexpr int AIT = 4, BIT = 2;
    constexpr int SP = BN + 4;

    extern __shared__ char smem_raw[];
    float* stg = (float*)smem_raw;
    uint32_t smbase = smem_u32(smem_raw);

    int tid = threadIdx.x, wid = tid >> 5, lane = tid & 31;
    int gid = lane >> 2, tig = lane & 3;
    int seg = lane >> 3, sl = lane & 7;
    int wm0 = (wid >> 2) * 32, wn0 = (wid & 3) * 32;

    int row0 = blockIdx.y * BM, col0 = blockIdx.x * BN;
    const h16* AhP = Ah_ + (long)row0 * lda;
    const h16* AlP = Al_ + (long)row0 * lda;
    const h16* BhP = Bh_ + (long)col0 * ldb;

    const h16* asrc[AIT]; uint32_t adst[AIT];
#pragma unroll
    for (int i = 0; i < AIT; i++) {
        int idx = tid + i * 512;
        int lo = idx >= BM * 8;
        int w = idx - lo * BM * 8;
        int r = w >> 3, kc = w & 7;
        asrc[i] = (lo ? AlP : AhP) + (long)r * lda + kc * 8;
        adst[i] = smbase + 2u * ((lo ? OAl : OAh) + r * PA + kc * 8);
    }
    const h16* bsrc[BIT]; uint32_t bdst[BIT];
#pragma unroll
    for (int i = 0; i < BIT; i++) {
        int idx = tid + i * 512;
        int r = idx >> 3, kc = idx & 7;
        bsrc[i] = BhP + (long)r * ldb + kc * 8;
        bdst[i] = smbase + 2u * (OBh + r * PA + kc * 8);
    }

    uint32_t aadr_h[2], aadr_l[2], badr[2];
#pragma unroll
    for (int mi = 0; mi < 2; mi++) {
        int rowA = wm0 + mi * 16 + (seg & 1) * 8 + sl;
        int colA = (seg >> 1) * 8;
        aadr_h[mi] = smbase + 2u * (OAh + rowA * PA + colA);
        aadr_l[mi] = smbase + 2u * (OAl + rowA * PA + colA);
    }
#pragma unroll
    for (int nj = 0; nj < 2; nj++) {
        int rowB = wn0 + nj * 16 + (seg >> 1) * 8 + sl;
        int colB = (seg & 1) * 8;
        badr[nj] = smbase + 2u * (OBh + rowB * PA + colB);
    }

    float acc[2][4][4];
#pragma unroll
    for (int mi = 0; mi < 2; mi++)
#pragma unroll
        for (int ni = 0; ni < 4; ni++)
#pragma unroll
            for (int j = 0; j < 4; j++) acc[mi][ni][j] = 0.f;

    const int NS = K / BK;
    {
#pragma unroll
        for (int i = 0; i < AIT; i++) cpa16(adst[i], asrc[i]);
#pragma unroll
        for (int i = 0; i < BIT; i++) cpa16(bdst[i], bsrc[i]);
        cp_commit();
    }
    for (int s = 0; s < NS; s++) {
        if (s + 1 < NS) {
            long ko = (long)(s + 1) * BK;
            uint32_t boff = ((s + 1) & 1) * (uint32_t)(SBUF * 2);
#pragma unroll
            for (int i = 0; i < AIT; i++) cpa16(adst[i] + boff, asrc[i] + ko);
#pragma unroll
            for (int i = 0; i < BIT; i++) cpa16(bdst[i] + boff, bsrc[i] + ko);
            cp_commit();
            cp_wait<1>();
        } else {
            cp_wait<0>();
        }
        __syncthreads();
        uint32_t soff = (s & 1) * (uint32_t)(SBUF * 2);
#pragma unroll
        for (int kk = 0; kk < 4; kk++) {
            uint32_t off = soff + 32u * kk;
            uint32_t ah[2][4], al[2][4], bh[2][4];
#pragma unroll
            for (int mi = 0; mi < 2; mi++) {
                ldmx4(ah[mi], aadr_h[mi] + off);
                ldmx4(al[mi], aadr_l[mi] + off);
            }
#pragma unroll
            for (int nj = 0; nj < 2; nj++) ldmx4(bh[nj], badr[nj] + off);
#pragma unroll
            for (int mi = 0; mi < 2; mi++)
#pragma unroll
                for (int ni = 0; ni < 4; ni++) {
                    int nj = ni >> 1, hf = (ni & 1) * 2;
                    mma_f16(acc[mi][ni], ah[mi], &bh[nj][hf]);
                    mma_f16(acc[mi][ni], al[mi], &bh[nj][hf]);
                }
        }
        __syncthreads();
    }

#pragma unroll
    for (int mi = 0; mi < 2; mi++)
#pragma unroll
        for (int ni = 0; ni < 4; ni++) {
            int r = wm0 + mi * 16 + gid;
            int c = wn0 + ni * 8 + tig * 2;
            stg[r * SP + c]           = acc[mi][ni][0];
            stg[r * SP + c + 1]       = acc[mi][ni][1];
            stg[(r + 8) * SP + c]     = acc[mi][ni][2];
            stg[(r + 8) * SP + c + 1] = acc[mi][ni][3];
        }
    __syncthreads();
#pragma unroll
    for (int i = 0; i < 8; i++) {
        int idx = tid + i * 512;
        int row = idx >> 5, c4 = (idx & 31) * 4;
        float4 v = *(const float4*)(stg + row * SP + c4);
        int col = col0 + c4;
        if (bias) {
            float4 bv = *(const float4*)&bias[col];
            v.x += bv.x; v.y += bv.y; v.z += bv.z; v.w += bv.w;
        }
        *(float4*)&Cf[(long)(row0 + row) * ldc + col] = v;
    }
}

// ===========================================================================
// Fused attention: per (b,h,q-tile 128): S = Qc@Rc^T (regs), sumsq, U += S@Hv,
// then U / max(||row||,eps) -> Ao split. 512 threads, 16 warps (4m x 4n).
// A-side split fp16; Rc/Hv fp16-rounded. 2 MMAs per tile.
// ===========================================================================
#define NT 32            // r-tiles of 64
#define QT 128
#define PQ 136
#define PH 72
#define STG_E (64*PQ + 64*PH)        // 13312 elems per stage
#define ORH 0
#define OHH (64*PQ)
#define OQH (2*STG_E)
#define OQL (2*STG_E + QT*PQ)
#define FA_SMEM ((2*STG_E + 2*QT*PQ) * 2)   // 122,880 bytes

__global__ void __launch_bounds__(512, 1)
fused_attn_k(const h16* __restrict__ Qch, const h16* __restrict__ Qcl,
             const h16* __restrict__ Rch, const h16* __restrict__ Hth,
             h16* __restrict__ Aoh, h16* __restrict__ Aol)
{
    extern __shared__ char smem_raw[];
    uint32_t smbase = smem_u32(smem_raw);

    int tid = threadIdx.x, wid = tid >> 5, lane = tid & 31;
    int gid = lane >> 2, tig = lane & 3;
    int seg = lane >> 3, sl = lane & 7;
    int mw = wid >> 2, nw = wid & 3;

    int qt = blockIdx.x, z = blockIdx.z;
    int b = z >> 4, h = z & 15;
    int row0 = qt * QT;
    long qtok = ((long)(b * Sv + row0)) * 2048 + h * 128;
    long zHv = (long)z * HD * Sv;

    // ---- Qc prologue (hi+lo, 128 rows x 128 cols) ----
#pragma unroll
    for (int i = 0; i < 8; i++) {
        int idx = tid + i * 512;
        int comp = idx >> 11;
        int w = idx & 2047;
        int r = w >> 4, kc = w & 15;
        const h16* src = (comp ? Qcl : Qch) + qtok + (long)r * 2048 + kc * 8;
        cpa16(smbase + 2u * ((comp ? OQL : OQH) + r * PQ + kc * 8), src);
    }
    // ---- stage 0: Rc hi (2 iters), Hv hi (1 iter) ----
    {
        long rtok = ((long)(b * Sv)) * 2048 + h * 128;
#pragma unroll
        for (int i = 0; i < 2; i++) {
            int idx = tid + i * 512;
            int r = idx >> 4, kc = idx & 15;
            cpa16(smbase + 2u * (ORH + r * PQ + kc * 8), Rch + rtok + (long)r * 2048 + kc * 8);
        }
        {
            int n = tid >> 3, kc = tid & 7;
            cpa16(smbase + 2u * (OHH + n * PH + kc * 8), Hth + zHv + (long)n * 2048 + kc * 8);
        }
        cp_commit();
    }

    uint32_t qadr_h[2], qadr_l[2];
#pragma unroll
    for (int mi = 0; mi < 2; mi++) {
        int rowA = mw * 32 + mi * 16 + (seg & 1) * 8 + sl;
        int colA = (seg >> 1) * 8;
        qadr_h[mi] = smbase + 2u * (OQH + rowA * PQ + colA);
        qadr_l[mi] = smbase + 2u * (OQL + rowA * PQ + colA);
    }
    uint32_t radr;
    {
        int rowB = nw * 16 + (seg >> 1) * 8 + sl;
        int colB = (seg & 1) * 8;
        radr = smbase + 2u * (ORH + rowB * PQ + colB);
    }
    uint32_t hadr[4];
#pragma unroll
    for (int nj = 0; nj < 4; nj++) {
        int rowH = nj * 16 + (seg >> 1) * 8 + sl;
        int colH = (seg & 1) * 8 + nw * 16;
        hadr[nj] = smbase + 2u * (OHH + rowH * PH + colH);
    }

    float U[2][8][4];
#pragma unroll
    for (int mi = 0; mi < 2; mi++)
#pragma unroll
        for (int ni = 0; ni < 8; ni++)
#pragma unroll
            for (int j = 0; j < 4; j++) U[mi][ni][j] = 0.f;
    float sqacc[2][2] = {{0.f, 0.f}, {0.f, 0.f}};

    for (int t = 0; t < NT; t++) {
        if (t + 1 < NT) {
            uint32_t boff = ((t + 1) & 1) * (uint32_t)(STG_E * 2);
            long rtok = ((long)(b * Sv + (t + 1) * 64)) * 2048 + h * 128;
            long hoff = zHv + (t + 1) * 64;
#pragma unroll
            for (int i = 0; i < 2; i++) {
                int idx = tid + i * 512;
                int r = idx >> 4, kc = idx & 15;
                cpa16(smbase + boff + 2u * (ORH + r * PQ + kc * 8),
                      Rch + rtok + (long)r * 2048 + kc * 8);
            }
            {
                int n = tid >> 3, kc = tid & 7;
                cpa16(smbase + boff + 2u * (OHH + n * PH + kc * 8),
                      Hth + hoff + (long)n * 2048 + kc * 8);
            }
            cp_commit();
            cp_wait<1>();
        } else {
            cp_wait<0>();
        }
        __syncthreads();
        uint32_t soff = (t & 1) * (uint32_t)(STG_E * 2);

        // ---- Phase A: S (128q x 64r); warp rows mw*32..+32, cols nw*16..+16
        float sacc[2][2][4];
#pragma unroll
        for (int mi = 0; mi < 2; mi++)
#pragma unroll
            for (int ni = 0; ni < 2; ni++)
#pragma unroll
                for (int j = 0; j < 4; j++) sacc[mi][ni][j] = 0.f;
#pragma unroll
        for (int kk = 0; kk < 8; kk++) {
            uint32_t koff = 32u * kk;
            uint32_t ah[2][4], al[2][4], bh[4];
#pragma unroll
            for (int mi = 0; mi < 2; mi++) {
                ldmx4(ah[mi], qadr_h[mi] + koff);
                ldmx4(al[mi], qadr_l[mi] + koff);
            }
            ldmx4(bh, radr + soff + koff);
#pragma unroll
            for (int mi = 0; mi < 2; mi++)
#pragma unroll
                for (int ni = 0; ni < 2; ni++) {
                    mma_f16(sacc[mi][ni], ah[mi], &bh[ni * 2]);
                    mma_f16(sacc[mi][ni], al[mi], &bh[ni * 2]);
                }
        }
        // ---- sumsq ----
#pragma unroll
        for (int mi = 0; mi < 2; mi++) {
            float s0 = 0.f, s1 = 0.f;
#pragma unroll
            for (int ni = 0; ni < 2; ni++) {
                s0 += sacc[mi][ni][0] * sacc[mi][ni][0] + sacc[mi][ni][1] * sacc[mi][ni][1];
                s1 += sacc[mi][ni][2] * sacc[mi][ni][2] + sacc[mi][ni][3] * sacc[mi][ni][3];
            }
            sqacc[mi][0] += s0; sqacc[mi][1] += s1;
        }
        // ---- Phase B: U += S(split) @ Hv (warp k-slice = its 16 S-cols)
        uint32_t a2h[2][4], a2l[2][4];
#pragma unroll
        for (int mi = 0; mi < 2; mi++) {
            split2h(sacc[mi][0][0], sacc[mi][0][1], a2h[mi][0], a2l[mi][0]);
            split2h(sacc[mi][0][2], sacc[mi][0][3], a2h[mi][1], a2l[mi][1]);
            split2h(sacc[mi][1][0], sacc[mi][1][1], a2h[mi][2], a2l[mi][2]);
            split2h(sacc[mi][1][2], sacc[mi][1][3], a2h[mi][3], a2l[mi][3]);
        }
#pragma unroll
        for (int nj = 0; nj < 4; nj++) {
            uint32_t bh2[4];
            ldmx4(bh2, hadr[nj] + soff);
#pragma unroll
            for (int hf = 0; hf < 2; hf++) {
                int ni = nj * 2 + hf;
#pragma unroll
                for (int mi = 0; mi < 2; mi++) {
                    mma_f16(U[mi][ni], a2h[mi], &bh2[hf * 2]);
                    mma_f16(U[mi][ni], a2l[mi], &bh2[hf * 2]);
                }
            }
        }
        __syncthreads();
    }

    // ================= epilogue =================
    float* Ured = (float*)smem_raw;
    float* sq = (float*)(smem_raw + QT * 68 * 4);
    if (tid < QT) sq[tid] = 0.f;
    __syncthreads();
#pragma unroll
    for (int mi = 0; mi < 2; mi++)
#pragma unroll
        for (int hh = 0; hh < 2; hh++) {
            float v = sqacc[mi][hh];
            v += __shfl_xor_sync(0xFFFFFFFF, v, 1);
            v += __shfl_xor_sync(0xFFFFFFFF, v, 2);
            if (tig == 0) atomicAdd(&sq[mw * 32 + mi * 16 + gid + hh * 8], v);
        }
    __syncthreads();
    if (tid < QT) sq[tid] = 1.0f / fmaxf(sqrtf(sq[tid]), NORM_EPS);
    for (int w = 0; w < 4; w++) {
        if (nw == w) {
#pragma unroll
            for (int mi = 0; mi < 2; mi++)
#pragma unroll
                for (int ni = 0; ni < 8; ni++) {
                    int r = mw * 32 + mi * 16 + gid;
                    int c = ni * 8 + tig * 2;
                    if (w == 0) {
                        Ured[r * 68 + c]           = U[mi][ni][0];
                        Ured[r * 68 + c + 1]       = U[mi][ni][1];
                        Ured[(r + 8) * 68 + c]     = U[mi][ni][2];
                        Ured[(r + 8) * 68 + c + 1] = U[mi][ni][3];
                    } else {
                        Ured[r * 68 + c]           += U[mi][ni][0];
                        Ured[r * 68 + c + 1]       += U[mi][ni][1];
                        Ured[(r + 8) * 68 + c]     += U[mi][ni][2];
                        Ured[(r + 8) * 68 + c + 1] += U[mi][ni][3];
                    }
                }
        }
        __syncthreads();
    }
#pragma unroll
    for (int i = 0; i < 4; i++) {
        int idx = tid + i * 512;
        int r = idx >> 4, c4 = (idx & 15) * 4;
        float sc = sq[r];
        float4 v = *(const float4*)(Ured + r * 68 + c4);
        v.x *= sc; v.y *= sc; v.z *= sc; v.w *= sc;
        uint2 hh, ll;
        split4h(v, hh, ll);
        long gpos = ((long)(b * Sv + row0 + r)) * DM + h * 64 + c4;
        *(uint2*)&Aoh[gpos] = hh;
        *(uint2*)&Aol[gpos] = ll;
    }
}

// ===========================================================================
// small kernels
// ===========================================================================
__global__ void split_k(const float* __restrict__ x, h16* __restrict__ h,
                        h16* __restrict__ l, long n4)
{
    long i = (long)blockIdx.x * 256 + threadIdx.x;
    if (i >= n4) return;
    float4 v = *(const float4*)&x[i * 4];
    uint2 hh, ll;
    split4h(v, hh, ll);
    *(uint2*)&h[i * 4] = hh;
    *(uint2*)&l[i * 4] = ll;
}

// transpose + round-to-fp16 (B-side operands: weights, HvT)
__global__ void transpose_round_k(const float* __restrict__ in,
                                  h16* __restrict__ oh,
                                  long ldi, long ldo, int H,
                                  long sIb, long sIh, long sOz)
{
    __shared__ float t[32][33];
    int z = blockIdx.z, b = z / H, h = z - b * H;
    in += (long)b * sIb + (long)h * sIh;
    oh += (long)z * sOz;
    int x0 = blockIdx.x * 32, y0 = blockIdx.y * 32;
    int tx = threadIdx.x & 31, ty = threadIdx.x >> 5;
#pragma unroll
    for (int i = 0; i < 4; i++)
        t[ty + i * 8][tx] = in[(long)(y0 + ty + i * 8) * ldi + x0 + tx];
    __syncthreads();
#pragma unroll
    for (int i = 0; i < 4; i++)
        oh[(long)(x0 + ty + i * 8) * ldo + y0 + tx] = __float2half(t[tx][ty + i * 8]);
}

__global__ void layernorm_split_k(const float* __restrict__ Z,
                                  h16* __restrict__ oh, h16* __restrict__ ol,
                                  const float* __restrict__ g, const float* __restrict__ be)
{
    __shared__ float red[256];
    int tid = threadIdx.x;
    const float* row = Z + (long)blockIdx.x * DL;
    float v[4];
#pragma unroll
    for (int t = 0; t < 4; t++) v[t] = row[tid + t * 256];
    float s = v[0] + v[1] + v[2] + v[3];
    red[tid] = s; __syncthreads();
    for (int off = 128; off > 0; off >>= 1) {
        if (tid < off) red[tid] += red[tid + off];
        __syncthreads();
    }
    float mu = red[0] * (1.0f / DL);
    __syncthreads();
    float vs = 0.f;
#pragma unroll
    for (int t = 0; t < 4; t++) { float d = v[t] - mu; vs += d * d; }
    red[tid] = vs; __syncthreads();
    for (int off = 128; off > 0; off >>= 1) {
        if (tid < off) red[tid] += red[tid + off];
        __syncthreads();
    }
    float rstd = rsqrtf(red[0] * (1.0f / DL) + LN_EPS);
    long base = (long)blockIdx.x * DL;
#pragma unroll
    for (int t = 0; t < 4; t++) {
        int i = tid + t * 256;
        float o = (v[t] - mu) * rstd * g[i] + be[i];
        h16 hv = __float2half(o);
        oh[base + i] = hv;
        ol[base + i] = __float2half(o - __half2float(hv));
    }
}

// phasor; lo output optional (Rc is a B operand -> hi only)
__global__ void phasor_split_k(const float* __restrict__ Qin, long ldq,
                               h16* __restrict__ oh, h16* __restrict__ ol,
                               const float* __restrict__ Wphi, const float* __restrict__ bphi)
{
    __shared__ float W[HD][HD];
    __shared__ float qrow[4][HD + 4];
    int tid = threadIdx.x;
    int j = tid & 63, g = tid >> 6;
    for (int i = tid; i < HD * HD; i += 256) W[i >> 6][i & 63] = Wphi[i];
    __syncthreads();
    const float* base = Qin + (long)blockIdx.x * ldq;
    long obase = (long)blockIdx.x * (NH * 2 * HD);
    float bj = bphi[j];
    for (int hb = 0; hb < NH; hb += 4) {
        int h = hb + g;
        qrow[g][j] = base[h * HD + j];
        __syncthreads();
        float phi = bj;
#pragma unroll 16
        for (int d = 0; d < HD; d++) phi += qrow[g][d] * W[d][j];
        float q = qrow[g][j];
        float sp, cp;
        sincosf(phi, &sp, &cp);
        float vc = q * cp, vsn = q * sp;
        h16 hc = __float2half(vc), hs = __float2half(vsn);
        long oc = obase + h * 2 * HD + j;
        oh[oc] = hc;
        oh[oc + HD] = hs;
        if (ol) {
            ol[oc] = __float2half(vc - __half2float(hc));
            ol[oc + HD] = __float2half(vsn - __half2float(hs));
        }
        __syncthreads();
    }
}

__global__ void concat3_k(const float* __restrict__ a, const float* __restrict__ b,
                          const float* __restrict__ c, float* __restrict__ o)
{
    int i = blockIdx.x * 256 + threadIdx.x;
    if (i < DM) o[i] = a[i];
    else if (i < 2 * DM) o[i] = b[i - DM];
    else if (i < 3 * DM) o[i] = c[i - 2 * DM];
}

// ===========================================================================
extern "C" void kernel_launch(void* const* d_in, const int* in_sizes, int n_in,
                              void* d_out, int out_size)
{
    const float* query = (const float*)d_in[0];
    const float* Wz   = (const float*)d_in[3];
    const float* bz   = (const float*)d_in[4];
    const float* ln_g = (const float*)d_in[5];
    const float* ln_b = (const float*)d_in[6];
    const float* Wq   = (const float*)d_in[7];
    const float* bq   = (const float*)d_in[8];
    const float* Wr   = (const float*)d_in[9];
    const float* br   = (const float*)d_in[10];
    const float* Wh   = (const float*)d_in[11];
    const float* bh   = (const float*)d_in[12];
    const float* Wphi = (const float*)d_in[13];
    const float* bphi = (const float*)d_in[14];
    const float* Wo   = (const float*)d_in[15];
    const float* bo   = (const float*)d_in[16];
    float* out = (float*)d_out;

    h16 *Qs_h, *Qs_l, *WT_h, *Zs_h, *Zs_l, *Qc_h, *Qc_l, *Rc_h, *HvT_h, *Ao_h, *Ao_l;
    float *Z, *QRH, *bqrh;
    cudaGetSymbolAddress((void**)&Qs_h, g_Qs_h); cudaGetSymbolAddress((void**)&Qs_l, g_Qs_l);
    cudaGetSymbolAddress((void**)&WT_h, g_WT_h);
    cudaGetSymbolAddress((void**)&Z,    g_Z);
    cudaGetSymbolAddress((void**)&Zs_h, g_Zs_h); cudaGetSymbolAddress((void**)&Zs_l, g_Zs_l);
    cudaGetSymbolAddress((void**)&QRH,  g_QRH);
    cudaGetSymbolAddress((void**)&bqrh, g_bqrh);
    cudaGetSymbolAddress((void**)&Qc_h, g_Qc_h); cudaGetSymbolAddress((void**)&Qc_l, g_Qc_l);
    cudaGetSymbolAddress((void**)&Rc_h, g_Rc_h);
    cudaGetSymbolAddress((void**)&HvT_h, g_HvT_h);
    cudaGetSymbolAddress((void**)&Ao_h, g_Ao_h); cudaGetSymbolAddress((void**)&Ao_l, g_Ao_l);

    const int SMG = (2 * 128 + 128) * 72 * 2 * 2;   // 110,592 B
    cudaFuncSetAttribute(gemm_ps, cudaFuncAttributeMaxDynamicSharedMemorySize, SMG);
    cudaFuncSetAttribute(fused_attn_k, cudaFuncAttributeMaxDynamicSharedMemorySize, FA_SMEM);

    dim3 blk(256), gblk(512);
    long szW = (long)DM * DL;

    // 0) transpose+round weights (fp16 hi); split query; combined bias
    transpose_round_k<<<dim3(32, 32, 1), blk>>>(Wz, WT_h + 0 * szW, DL, DM, 1, 0, 0, 0);
    transpose_round_k<<<dim3(32, 32, 1), blk>>>(Wq, WT_h + 1 * szW, DM, DL, 1, 0, 0, 0);
    transpose_round_k<<<dim3(32, 32, 1), blk>>>(Wr, WT_h + 2 * szW, DM, DL, 1, 0, 0, 0);
    transpose_round_k<<<dim3(32, 32, 1), blk>>>(Wh, WT_h + 3 * szW, DM, DL, 1, 0, 0, 0);
    transpose_round_k<<<dim3(32, 32, 1), blk>>>(Wo, WT_h + 4 * szW, DM, DM, 1, 0, 0, 0);
    split_k<<<(TOK * DM / 4 + 255) / 256, blk>>>(query, Qs_h, Qs_l, (long)TOK * DM / 4);
    concat3_k<<<12, blk>>>(bq, br, bh, bqrh);

    // 1) Z = query @ Wz + bz
    gemm_ps<<<dim3(DL / 128, TOK / 128, 1), gblk, SMG>>>(
        Qs_h, Qs_l, WT_h, bz, Z, DM, DM, DM, DL);

    // 2) LayerNorm -> split Zs
    layernorm_split_k<<<TOK, blk>>>(Z, Zs_h, Zs_l, ln_g, ln_b);

    // 3) fused Q|R|H projection (N=3072)
    gemm_ps<<<dim3(3 * DM / 128, TOK / 128, 1), gblk, SMG>>>(
        Zs_h, Zs_l, WT_h + szW, bqrh, QRH, DL, DL, DL, 3 * DM);

    // 4) phasor -> Qc split, Rc hi-only
    phasor_split_k<<<TOK, blk>>>(QRH,      3 * DM, Qc_h, Qc_l, Wphi, bphi);
    phasor_split_k<<<TOK, blk>>>(QRH + DM, 3 * DM, Rc_h, (h16*)nullptr, Wphi, bphi);

    // 5) Hv^T per (b,h), fp16-rounded (Hv = QRH cols [2048,3072))
    transpose_round_k<<<dim3(HD / 32, Sv / 32, Bv * NH), blk>>>(
        QRH + 2 * DM, HvT_h, 3 * DM, Sv, NH, (long)Sv * 3 * DM, HD, (long)HD * Sv);

    // 6) fused attention -> Ao split
    fused_attn_k<<<dim3(Sv / QT, 1, Bv * NH), gblk, FA_SMEM>>>(
        Qc_h, Qc_l, Rc_h, HvT_h, Ao_h, Ao_l);

    // 7) out = Ao @ Wo + bo
    gemm_ps<<<dim3(DM / 128, TOK / 128, 1), gblk, SMG>>>(
        Ao_h, Ao_l, WT_h + 4 * szW, bo, out, DM, DM, DM, DM);
}